// round 13
// baseline (speedup 1.0000x reference)
#include <cuda_runtime.h>
#include <math.h>
#include <stdint.h>
#include <cuda_fp16.h>

#define NN 30000
#define NP 30080          // 235 * 128
#define EE 200000
#define FF 256
#define HH 8
#define DD 32
#define LL 3

typedef unsigned long long u64;
#define NPF ((size_t)NP * 256)

// tcgen05 path only on arch-specific ('a') compilation passes.
#if defined(__CUDA_ARCH__) && (defined(__CUDA_ARCH_FEAT_SM103_ALL) || defined(__CUDA_ARCH_FEAT_SM100_ALL) || defined(__CUDA_ARCH_SPECIFIC__))
#define TC_PATH 1
#else
#define TC_PATH 0
#endif

// ---------------- scratch (static device memory; no allocation) ----------------
__device__ float  g_x  [2 * NPF];            // fp32 x (residual source); padded rows stay 0
__device__ float  g_kqv[2 * (size_t)NP * 768]; // ke | q | ve  (fp32, attn operands)
__device__ __half g_xh [2 * NPF];            // hi(x)   - kqv GEMM A side
__device__ __half g_xl [2 * NPF];            // lo(x)
__device__ __half g_aggh[2 * NPF];           // hi(gelu(agg)) - out GEMM A side
__device__ __half g_aggl[2 * NPF];
__device__ __half g_Weh[6 * (size_t)768 * 256];  // folded W_kqv^T hi: [lt][n][k]
__device__ __half g_Wel[6 * (size_t)768 * 256];
__device__ __half g_Woh[6 * (size_t)256 * 256];  // W_out^T hi
__device__ __half g_Wol[6 * (size_t)256 * 256];
__device__ float  g_be [6 * 3 * FF];

__device__ int g_deg[2 * NP];
__device__ int g_cur[2 * NP];
__device__ int g_off[2 * (NP + 1)];
__device__ int g_eid[2 * EE];
__device__ int g_srt[2 * EE];

__device__ __forceinline__ float gelu_exact(float x) {
    return 0.5f * x * (1.0f + erff(x * 0.70710678118654752440f));
}
__device__ __forceinline__ void ffma2(u64& d, u64 a, u64 b) {
    asm("fma.rn.f32x2 %0, %1, %2, %0;" : "+l"(d) : "l"(a), "l"(b));
}
__device__ __forceinline__ u64 dupf(float x) {
    u64 r; asm("mov.b64 %0, {%1, %1};" : "=l"(r) : "f"(x)); return r;
}
__device__ __forceinline__ uint32_t smem_u32(const void* p) {
    uint32_t a;
    asm("{ .reg .u64 t; cvta.to.shared.u64 t, %1; cvt.u32.u64 %0, t; }" : "=r"(a) : "l"(p));
    return a;
}
__device__ __forceinline__ void split_hl(float v, __half& h, __half& l) {
    h = __float2half_rn(v);
    l = __float2half_rn(v - __half2float(h));
}
__device__ __forceinline__ uint32_t pack2(__half a, __half b) {
    __half2 p = __halves2half2(a, b);
    return *(uint32_t*)&p;
}

#if TC_PATH
// ---------------- tcgen05 helpers ----------------
__device__ __forceinline__ uint32_t swz(uint32_t b) { return b ^ ((b >> 3) & 0x70u); }
__device__ __forceinline__ u64 mkdesc(uint32_t addr) {
    const u64 base = (2ULL << 61) | (1ULL << 46) | (64ULL << 32) | (1ULL << 16);  // SW128, v1, SBO=64, LBO=1
    return base | ((u64)(addr >> 4) & 0x3FFFULL);
}
// idesc kind::f16 (fp16 in, fp32 acc): dF32(1<<4) | N128(16<<17) | M128(8<<24)
#define IDESC_F16 0x8200010u

__device__ __forceinline__ void mma_f16(uint32_t d, u64 ad, u64 bd, uint32_t en) {
    asm volatile(
        "{\n\t.reg .pred p;\n\t"
        "setp.ne.u32 p, %4, 0;\n\t"
        "tcgen05.mma.cta_group::1.kind::f16 [%0], %1, %2, %3, {%5, %5, %5, %5}, p;\n\t"
        "}"
        :: "r"(d), "l"(ad), "l"(bd), "r"(IDESC_F16), "r"(en), "r"(0u)
        : "memory");
}
__device__ __forceinline__ void tmem_alloc(uint32_t dst_smem, uint32_t ncols) {
    asm volatile("tcgen05.alloc.cta_group::1.sync.aligned.shared::cta.b32 [%0], %1;"
                 :: "r"(dst_smem), "r"(ncols) : "memory");
}
__device__ __forceinline__ void tmem_relinq() {
    asm volatile("tcgen05.relinquish_alloc_permit.cta_group::1.sync.aligned;");
}
__device__ __forceinline__ void tmem_dealloc(uint32_t base, uint32_t ncols) {
    asm volatile("tcgen05.dealloc.cta_group::1.sync.aligned.b32 %0, %1;" :: "r"(base), "r"(ncols));
}
__device__ __forceinline__ void mbar_init(uint32_t mbar, uint32_t cnt) {
    asm volatile("mbarrier.init.shared.b64 [%0], %1;" :: "r"(mbar), "r"(cnt) : "memory");
}
__device__ __forceinline__ void tc_commit(uint32_t mbar) {
    asm volatile("tcgen05.commit.cta_group::1.mbarrier::arrive::one.shared::cluster.b64 [%0];"
                 :: "r"(mbar) : "memory");
}
__device__ __forceinline__ void mbar_wait(uint32_t mbar, uint32_t parity) {
    uint32_t done = 0;
    do {
        asm volatile(
            "{\n\t.reg .pred p;\n\t"
            "mbarrier.try_wait.parity.acquire.cta.shared::cta.b64 p, [%1], %2, 0x989680;\n\t"
            "selp.b32 %0, 1, 0, p;\n\t}"
            : "=r"(done) : "r"(mbar), "r"(parity) : "memory");
    } while (!done);
}
__device__ __forceinline__ void fence_async_smem() {
    asm volatile("fence.proxy.async.shared::cta;" ::: "memory");
}
__device__ __forceinline__ void tc_fence_after() {
    asm volatile("tcgen05.fence::after_thread_sync;" ::: "memory");
}
__device__ __forceinline__ void tc_fence_before() {
    asm volatile("tcgen05.fence::before_thread_sync;" ::: "memory");
}
__device__ __forceinline__ void tc_wait_ld() {
    asm volatile("tcgen05.wait::ld.sync.aligned;" ::: "memory");
}
__device__ __forceinline__ void ldtm32(uint32_t (&r)[32], uint32_t tmem_addr) {
    asm volatile(
        "tcgen05.ld.sync.aligned.32x32b.x32.b32 "
        "{%0, %1, %2, %3, %4, %5, %6, %7, "
        " %8, %9, %10, %11, %12, %13, %14, %15, "
        " %16, %17, %18, %19, %20, %21, %22, %23, "
        " %24, %25, %26, %27, %28, %29, %30, %31}, [%32];"
        : "=r"(r[0]),  "=r"(r[1]),  "=r"(r[2]),  "=r"(r[3]),
          "=r"(r[4]),  "=r"(r[5]),  "=r"(r[6]),  "=r"(r[7]),
          "=r"(r[8]),  "=r"(r[9]),  "=r"(r[10]), "=r"(r[11]),
          "=r"(r[12]), "=r"(r[13]), "=r"(r[14]), "=r"(r[15]),
          "=r"(r[16]), "=r"(r[17]), "=r"(r[18]), "=r"(r[19]),
          "=r"(r[20]), "=r"(r[21]), "=r"(r[22]), "=r"(r[23]),
          "=r"(r[24]), "=r"(r[25]), "=r"(r[26]), "=r"(r[27]),
          "=r"(r[28]), "=r"(r[29]), "=r"(r[30]), "=r"(r[31])
        : "r"(tmem_addr));
}

// Copy a [128 x 64] fp16 tile (src row stride 256 halves, cols c0..c0+63) into an
// SW128 smem tile (128B rows). Pure LDG.128 -> STS.128, no conversion.
__device__ __forceinline__ void load_tile_h(
    const __half* __restrict__ src, int rowbase, int c0, uint32_t dst, int tid)
{
#pragma unroll
    for (int pass = 0; pass < 4; pass++) {
        int row = pass * 32 + (tid >> 3);
        int j8  = (tid & 7) * 8;
        uint4 v = *(const uint4*)(src + (size_t)(rowbase + row) * 256 + c0 + j8);
        uint32_t sw = swz((uint32_t)row * 128u + (uint32_t)j8 * 2u);
        asm volatile("st.shared.v4.b32 [%0], {%1,%2,%3,%4};"
                     :: "r"(dst + sw), "r"(v.x), "r"(v.y), "r"(v.z), "r"(v.w) : "memory");
    }
}
#endif  // TC_PATH

// ---------------- one-time split of harness inputs x0/x1 into hi/lo fp16 + fp32 copy ----
__global__ void split_x_kernel(const float* __restrict__ x0, const float* __restrict__ x1) {
    size_t i = (size_t)blockIdx.x * 256 + threadIdx.x;
    if (i < (size_t)NN * 256) {
        float v0 = x0[i], v1 = x1[i];
        __half h, l;
        split_hl(v0, h, l); g_xh[i] = h; g_xl[i] = l;
        split_hl(v1, h, l); g_xh[NPF + i] = h; g_xl[NPF + i] = l;
        g_x[i] = v0; g_x[NPF + i] = v1;
    }
}

// ---------------- fold relation transforms into W_kqv (transposed, hi/lo fp16) ----------
__global__ void __launch_bounds__(256) fold_kernel(
    const float* __restrict__ Wk, const float* __restrict__ bk,
    const float* __restrict__ Ar, const float* __restrict__ Mr)
{
    int bx = blockIdx.x;
    int lt = bx >> 4;
    int part = (bx >> 3) & 1;
    int h = bx & 7;
    const float* A = (part ? Mr : Ar) + (size_t)lt * HH * DD * DD + h * DD * DD;
    __shared__ float sA[DD * DD];
    int tid = threadIdx.x;
    for (int i = tid; i < DD * DD; i += 256) sA[i] = A[i];
    __syncthreads();
    int e = tid & 31;
    int rg = tid >> 5;
    int col = (part ? 512 : 0) + h * 32;
    for (int r = rg * 32; r < rg * 32 + 32; r++) {
        const float* w = Wk + (size_t)lt * 256 * 768 + (size_t)r * 768 + col;
        float acc = 0.0f;
#pragma unroll
        for (int d = 0; d < 32; d++) acc = fmaf(w[d], sA[d * 32 + e], acc);
        size_t o = (size_t)lt * 768 * 256 + (size_t)(col + e) * 256 + r;
        __half hh, hl; split_hl(acc, hh, hl);
        g_Weh[o] = hh; g_Wel[o] = hl;
    }
    if (rg == 0) {
        const float* b = bk + (size_t)lt * 768 + col;
        float acc = 0.0f;
#pragma unroll
        for (int d = 0; d < 32; d++) acc = fmaf(b[d], sA[d * 32 + e], acc);
        g_be[lt * 768 + col + e] = acc;
    }
}

__global__ void foldq_kernel(const float* __restrict__ Wk, const float* __restrict__ bk,
                             const float* __restrict__ Wo) {
    int idx = blockIdx.x * 256 + threadIdx.x;
    if (idx < 6 * 256 * 256) {
        int lt = idx >> 16;
        int rem = idx & 65535;
        int c = rem >> 8;
        int r = rem & 255;
        float v = Wk[(size_t)lt * 256 * 768 + (size_t)r * 768 + 256 + c];
        size_t o = (size_t)lt * 768 * 256 + (size_t)(256 + c) * 256 + r;
        __half hh, hl; split_hl(v, hh, hl);
        g_Weh[o] = hh; g_Wel[o] = hl;
    } else if (idx < 2 * 6 * 256 * 256) {
        int i2 = idx - 6 * 256 * 256;
        int lt = i2 >> 16;
        int rem = i2 & 65535;
        int n = rem >> 8;
        int k = rem & 255;
        float v = Wo[(size_t)lt * 65536 + (size_t)k * 256 + n];
        size_t o = (size_t)lt * 65536 + (size_t)n * 256 + k;
        __half hh, hl; split_hl(v, hh, hl);
        g_Woh[o] = hh; g_Wol[o] = hl;
    }
    if (idx < 6 * 256) {
        int lt = idx >> 8, c = idx & 255;
        g_be[lt * 768 + 256 + c] = bk[lt * 768 + 256 + c];
    }
}

// ---------------- CSR build ----------------
__global__ void csr_zero_kernel() {
    int i = blockIdx.x * 256 + threadIdx.x;
    if (i < 2 * NP) { g_deg[i] = 0; g_cur[i] = 0; }
}
__global__ void csr_hist_kernel(const int* __restrict__ dst0, const int* __restrict__ dst1) {
    int e = blockIdx.x * 256 + threadIdx.x;
    if (e < EE) {
        atomicAdd(&g_deg[dst0[e]], 1);
        atomicAdd(&g_deg[NP + dst1[e]], 1);
    }
}
__global__ void __launch_bounds__(1024) csr_scan_kernel() {
    const int t = blockIdx.x;
    const int* deg = g_deg + t * NP;
    int* off = g_off + t * (NP + 1);
    const int tid = threadIdx.x;
    const int CH = 30;
    int base = tid * CH;
    int local[CH];
    int s = 0;
#pragma unroll
    for (int i = 0; i < CH; i++) {
        int idx = base + i;
        int v = (idx < NP) ? deg[idx] : 0;
        local[i] = s; s += v;
    }
    __shared__ int wsum[32];
    int lane = tid & 31, wid = tid >> 5;
    int ws = s;
#pragma unroll
    for (int o = 1; o < 32; o <<= 1) { int y = __shfl_up_sync(~0u, ws, o); if (lane >= o) ws += y; }
    if (lane == 31) wsum[wid] = ws;
    __syncthreads();
    if (wid == 0) {
        int v = wsum[lane];
#pragma unroll
        for (int o = 1; o < 32; o <<= 1) { int y = __shfl_up_sync(~0u, v, o); if (lane >= o) v += y; }
        wsum[lane] = v;
    }
    __syncthreads();
    int warpEx = (wid > 0) ? wsum[wid - 1] : 0;
    int ex = warpEx + ws - s;
#pragma unroll
    for (int i = 0; i < CH; i++) {
        int idx = base + i;
        if (idx < NP) off[idx] = ex + local[i];
    }
    if (tid == 1023) off[NP] = warpEx + ws;
}
__global__ void csr_scatter_kernel(const int* __restrict__ dst0, const int* __restrict__ dst1) {
    int e = blockIdx.x * 256 + threadIdx.x;
    if (e >= EE) return;
    int d0 = dst0[e];
    int p0 = g_off[d0] + atomicAdd(&g_cur[d0], 1);
    g_eid[p0] = e;
    int d1 = dst1[e];
    int p1 = g_off[(NP + 1) + d1] + atomicAdd(&g_cur[NP + d1], 1);
    g_eid[EE + p1] = e;
}
__global__ void csr_sort_kernel(const int* __restrict__ s0, const int* __restrict__ s1) {
    int idx = blockIdx.x * 256 + threadIdx.x;
    if (idx >= 2 * NP) return;
    int t = (idx >= NP) ? 1 : 0;
    int d = idx - t * NP;
    const int* off = g_off + t * (NP + 1);
    int b = off[d], e = off[d + 1];
    int* a = g_eid + t * EE;
    for (int i = b + 1; i < e; i++) {
        int key = a[i];
        int j = i - 1;
        while (j >= b && a[j] > key) { a[j + 1] = a[j]; j--; }
        a[j + 1] = key;
    }
    const int* sarr = t ? s1 : s0;
    int* o = g_srt + t * EE;
    for (int i = b; i < e; i++) o[i] = sarr[a[i]];
}

// ---------------- unified GEMM: C[M,Nc] = A[M,256] @ B[Nc,256]^T + bias (+ epilogue) -----
// Operands pre-split into hi/lo fp16 arrays; loader is pure LDG->STS.
// TC path: 12 fp16 MMAs per K=64 chunk (hi*hi + lo*hi + hi*lo), 4 chunks, 64KB single
// stage -> 3 CTAs/SM. EPI epilogue also emits hi/lo split of the result (next-layer A).
#define SMEM_DYN (65536 + 1024)

template <bool EPI>
__global__ void __launch_bounds__(256) gemm_kernel(
    const __half* __restrict__ Ah, const __half* __restrict__ Al,
    const __half* __restrict__ Bh, const __half* __restrict__ Bl,
    const float* __restrict__ bias,
    float* __restrict__ C0, float* __restrict__ C1, int Nc,
    __half* __restrict__ Ch, __half* __restrict__ Cl,
    size_t sB_, size_t sb_,
    const float* __restrict__ xr0, const float* __restrict__ xr1,
    const float* __restrict__ skp)
{
    const int z = blockIdx.z;
    Ah += (size_t)z * NPF; Al += (size_t)z * NPF;
    Bh += (size_t)z * sB_; Bl += (size_t)z * sB_;
    bias += (size_t)z * sb_;
    float* C = z ? C1 : C0;
    const float* xres = z ? xr1 : xr0;
    if (EPI) { skp += z; Ch += (size_t)z * NPF; Cl += (size_t)z * NPF; }

    extern __shared__ char dsm[];
    const int tid = threadIdx.x;
    const int m0 = blockIdx.y * 128;
    const int n0 = blockIdx.x * 128;

#if TC_PATH
    uint32_t st = (smem_u32(dsm) + 1023u) & ~1023u;   // Ahi | Alo | Bhi | Blo (16KB each)

    __shared__ uint32_t s_tmem;
    __shared__ __align__(8) u64 s_mbar;
    const int wid = tid >> 5;
    const int lane = tid & 31;

    if (wid == 0) { tmem_alloc(smem_u32(&s_tmem), 128); tmem_relinq(); }
    if (tid == 0) mbar_init(smem_u32(&s_mbar), 1);
    __syncthreads();
    uint32_t tmem;
    asm volatile("ld.shared.b32 %0, [%1];" : "=r"(tmem) : "r"(smem_u32(&s_tmem)));
    const uint32_t mbar = smem_u32(&s_mbar);

    const u64 dA = mkdesc(st), dAl = mkdesc(st + 16384);
    const u64 dB = mkdesc(st + 32768), dBl = mkdesc(st + 49152);

    for (int c = 0; c < 4; c++) {
        if (c > 0) mbar_wait(mbar, (uint32_t)((c - 1) & 1));
        load_tile_h(Ah, m0, c * 64, st,         tid);
        load_tile_h(Al, m0, c * 64, st + 16384, tid);
        load_tile_h(Bh, n0, c * 64, st + 32768, tid);
        load_tile_h(Bl, n0, c * 64, st + 49152, tid);
        __syncthreads();
        if (tid == 0) {
            fence_async_smem();
#pragma unroll
            for (int k = 0; k < 4; k++) {              // 4 k-steps of 16 within the 64-chunk
                uint32_t en = (c > 0 || k > 0) ? 1u : 0u;
                mma_f16(tmem, dA  + 2 * k, dB  + 2 * k, en);
                mma_f16(tmem, dAl + 2 * k, dB  + 2 * k, 1u);
                mma_f16(tmem, dA  + 2 * k, dBl + 2 * k, 1u);
            }
            tc_commit(mbar);
        }
    }
    mbar_wait(mbar, 1u);   // 4th commit completion
    tc_fence_after();

    float sAv = 0.0f;
    if (EPI) sAv = 1.0f / (1.0f + __expf(-skp[0]));
    if (wid < 4) {
        const int m = m0 + wid * 32 + lane;
        const int mr = min(m, NN - 1);
#pragma unroll
        for (int g = 0; g < 4; g++) {
            uint32_t r[32];
            ldtm32(r, tmem + g * 32);
            tc_wait_ld();
            const int nb = n0 + g * 32;
            float ov[32];
#pragma unroll
            for (int j = 0; j < 32; j++) {
                float o = __uint_as_float(r[j]) + bias[nb + j];
                if (EPI) {
                    o = sAv * o + (1.0f - sAv) * xres[(size_t)mr * FF + nb + j];
                    o = fmaxf(o, 0.0f);
                }
                ov[j] = o;
            }
            if (m < NN) {
#pragma unroll
                for (int j = 0; j < 32; j += 4)
                    *(float4*)&C[(size_t)m * Nc + nb + j] = make_float4(ov[j], ov[j+1], ov[j+2], ov[j+3]);
                if (EPI) {
#pragma unroll
                    for (int j = 0; j < 32; j += 8) {
                        __half hh[8], hl[8];
#pragma unroll
                        for (int q = 0; q < 8; q++) split_hl(ov[j + q], hh[q], hl[q]);
                        uint4 vh = make_uint4(pack2(hh[0], hh[1]), pack2(hh[2], hh[3]),
                                              pack2(hh[4], hh[5]), pack2(hh[6], hh[7]));
                        uint4 vl = make_uint4(pack2(hl[0], hl[1]), pack2(hl[2], hl[3]),
                                              pack2(hl[4], hl[5]), pack2(hl[6], hl[7]));
                        *(uint4*)&Ch[(size_t)m * 256 + nb + j] = vh;
                        *(uint4*)&Cl[(size_t)m * 256 + nb + j] = vl;
                    }
                }
            }
        }
        tc_fence_before();
    }
    __syncthreads();
    if (wid == 0) tmem_dealloc(tmem, 128);

#else   // ---------------- FFMA2 fallback (A/B reconstructed as hi+lo) ----------------
    float* As = (float*)dsm;
    float* Bs = (float*)dsm + 8 * 128;
    const int tx = tid & 15;
    const int ty = tid >> 4;

    u64 acc2[8][4];
#pragma unroll
    for (int i = 0; i < 8; i++)
#pragma unroll
        for (int j = 0; j < 4; j++) acc2[i][j] = 0ULL;

    const int ldRow = tid >> 1;
    const int ldK   = (tid & 1) * 4;
    const __half* Aph = Ah + (size_t)(m0 + ldRow) * 256 + ldK;
    const __half* Apl = Al + (size_t)(m0 + ldRow) * 256 + ldK;
    const __half* Bph = Bh + (size_t)(n0 + ldRow) * 256 + ldK;
    const __half* Bpl = Bl + (size_t)(n0 + ldRow) * 256 + ldK;

    for (int k0 = 0; k0 < 256; k0 += 8) {
        float av[4], bv[4];
#pragma unroll
        for (int q = 0; q < 4; q++) {
            av[q] = __half2float(Aph[k0 + q]) + __half2float(Apl[k0 + q]);
            bv[q] = __half2float(Bph[k0 + q]) + __half2float(Bpl[k0 + q]);
        }
        __syncthreads();
#pragma unroll
        for (int q = 0; q < 4; q++) {
            As[(ldK + q) * 128 + ldRow] = av[q];
            Bs[(ldK + q) * 128 + ldRow] = bv[q];
        }
        __syncthreads();
#pragma unroll
        for (int k = 0; k < 8; k++) {
            float4 a0 = *(const float4*)&As[k * 128 + ty * 8];
            float4 a1 = *(const float4*)&As[k * 128 + ty * 8 + 4];
            const u64* bp = (const u64*)&Bs[k * 128 + tx * 8];
            u64 br0 = bp[0], br1 = bp[1], br2 = bp[2], br3 = bp[3];
            u64 ad[8];
            ad[0] = dupf(a0.x); ad[1] = dupf(a0.y); ad[2] = dupf(a0.z); ad[3] = dupf(a0.w);
            ad[4] = dupf(a1.x); ad[5] = dupf(a1.y); ad[6] = dupf(a1.z); ad[7] = dupf(a1.w);
#pragma unroll
            for (int i = 0; i < 8; i++) {
                ffma2(acc2[i][0], ad[i], br0);
                ffma2(acc2[i][1], ad[i], br1);
                ffma2(acc2[i][2], ad[i], br2);
                ffma2(acc2[i][3], ad[i], br3);
            }
        }
    }

    float sAv = 0.0f;
    if (EPI) sAv = 1.0f / (1.0f + __expf(-skp[0]));
#pragma unroll
    for (int i = 0; i < 8; i++) {
        int m = m0 + ty * 8 + i;
        int mr = min(m, NN - 1);
#pragma unroll
        for (int j = 0; j < 4; j++) {
            float2 v = *(float2*)&acc2[i][j];
            int n = n0 + tx * 8 + 2 * j;
            float o0 = v.x + bias[n];
            float o1 = v.y + bias[n + 1];
            if (EPI) {
                o0 = sAv * o0 + (1.0f - sAv) * xres[(size_t)mr * FF + n];
                o1 = sAv * o1 + (1.0f - sAv) * xres[(size_t)mr * FF + n + 1];
                o0 = fmaxf(o0, 0.0f);
                o1 = fmaxf(o1, 0.0f);
            }
            if (m < NN) {
                C[(size_t)m * Nc + n] = o0;
                C[(size_t)m * Nc + n + 1] = o1;
                if (EPI) {
                    __half hh, hl;
                    split_hl(o0, hh, hl); Ch[(size_t)m * 256 + n] = hh; Cl[(size_t)m * 256 + n] = hl;
                    split_hl(o1, hh, hl); Ch[(size_t)m * 256 + n + 1] = hh; Cl[(size_t)m * 256 + n + 1] = hl;
                }
            }
        }
    }
#endif
}

// ---------------- fused edge attention: one warp per (dst type, dst node) ----------------
// Epilogue applies gelu and writes hi/lo fp16 agg (out-GEMM A operand) — no fp32 agg.
__global__ void __launch_bounds__(256) attn_kernel(const float* __restrict__ pr_l)
{
    int w = (blockIdx.x * 256 + threadIdx.x) >> 5;
    if (w >= 2 * NN) return;
    const int dt = (w >= NN) ? 1 : 0;
    const int node = w - dt * NN;
    const int et = 1 - dt;
    const float* kqv_d = g_kqv + (size_t)dt * NP * 768;
    const float* kqv_s = g_kqv + (size_t)et * NP * 768;
    const int* off = g_off + et * (NP + 1);
    const int* srt = g_srt + et * EE;

    const int lane = threadIdx.x & 31;
    const int h = lane >> 2;
    const int co = h * 32 + (lane & 3) * 8;

    const float* qr = kqv_d + (size_t)node * 768 + 256 + co;
    float4 q0 = *(const float4*)qr;
    float4 q1 = *(const float4*)(qr + 4);
    const float ph = pr_l[et * HH + h] * 0.17677669529663688110f;

    float m = -INFINITY, z = 0.0f;
    float4 a0 = {0.f, 0.f, 0.f, 0.f};
    float4 a1 = {0.f, 0.f, 0.f, 0.f};

    const int b = off[node], e2 = off[node + 1];
    for (int j = b; j < e2; j++) {
        int s = srt[j];
        const float* kr = kqv_s + (size_t)s * 768 + co;
        const float* vr = kr + 512;
        float4 k0 = *(const float4*)kr;
        float4 k1 = *(const float4*)(kr + 4);
        float4 v0 = *(const float4*)vr;
        float4 v1 = *(const float4*)(vr + 4);

        float dot = q0.x * k0.x + q0.y * k0.y + q0.z * k0.z + q0.w * k0.w
                  + q1.x * k1.x + q1.y * k1.y + q1.z * k1.z + q1.w * k1.w;
        dot += __shfl_xor_sync(0xffffffffu, dot, 1);
        dot += __shfl_xor_sync(0xffffffffu, dot, 2);
        float sc = dot * ph;

        float nm = fmaxf(m, sc);
        float scale = __expf(m - nm);
        float ea = __expf(sc - nm);
        z = z * scale + ea;
        a0.x = a0.x * scale + ea * v0.x;  a0.y = a0.y * scale + ea * v0.y;
        a0.z = a0.z * scale + ea * v0.z;  a0.w = a0.w * scale + ea * v0.w;
        a1.x = a1.x * scale + ea * v1.x;  a1.y = a1.y * scale + ea * v1.y;
        a1.z = a1.z * scale + ea * v1.z;  a1.w = a1.w * scale + ea * v1.w;
        m = nm;
    }

    float inv = (z > 0.0f) ? 1.0f / z : 0.0f;
    float o[8] = { a0.x * inv, a0.y * inv, a0.z * inv, a0.w * inv,
                   a1.x * inv, a1.y * inv, a1.z * inv, a1.w * inv };
    __half hh[8], hl[8];
#pragma unroll
    for (int j = 0; j < 8; j++) {
        float g = gelu_exact(o[j]);
        split_hl(g, hh[j], hl[j]);
    }
    size_t base = (size_t)dt * NPF + (size_t)node * 256 + co;
    *(uint4*)&g_aggh[base] = make_uint4(pack2(hh[0], hh[1]), pack2(hh[2], hh[3]),
                                        pack2(hh[4], hh[5]), pack2(hh[6], hh[7]));
    *(uint4*)&g_aggl[base] = make_uint4(pack2(hl[0], hl[1]), pack2(hl[2], hl[3]),
                                        pack2(hl[4], hl[5]), pack2(hl[6], hl[7]));
}

// ---------------- driver ----------------
extern "C" void kernel_launch(void* const* d_in, const int* in_sizes, int n_in,
                              void* d_out, int out_size)
{
    const float* x0 = (const float*)d_in[0];
    const float* x1 = (const float*)d_in[1];
    const int*   e_dr = (const int*)d_in[2];
    const int*   e_rd = (const int*)d_in[3];
    const float* Wk = (const float*)d_in[4];
    const float* bk = (const float*)d_in[5];
    const float* Ar = (const float*)d_in[6];
    const float* Mr = (const float*)d_in[7];
    const float* pr = (const float*)d_in[8];
    const float* Wo = (const float*)d_in[9];
    const float* bo = (const float*)d_in[10];
    const float* sk = (const float*)d_in[11];
    float* out = (float*)d_out;

    float *gx, *gkqv, *gbe;
    __half *gxh, *gxl, *gaggh, *gaggl, *gWeh, *gWel, *gWoh, *gWol;
    cudaGetSymbolAddress((void**)&gx,    g_x);
    cudaGetSymbolAddress((void**)&gkqv,  g_kqv);
    cudaGetSymbolAddress((void**)&gbe,   g_be);
    cudaGetSymbolAddress((void**)&gxh,   g_xh);
    cudaGetSymbolAddress((void**)&gxl,   g_xl);
    cudaGetSymbolAddress((void**)&gaggh, g_aggh);
    cudaGetSymbolAddress((void**)&gaggl, g_aggl);
    cudaGetSymbolAddress((void**)&gWeh,  g_Weh);
    cudaGetSymbolAddress((void**)&gWel,  g_Wel);
    cudaGetSymbolAddress((void**)&gWoh,  g_Woh);
    cudaGetSymbolAddress((void**)&gWol,  g_Wol);

    cudaFuncSetAttribute(gemm_kernel<false>, cudaFuncAttributeMaxDynamicSharedMemorySize, SMEM_DYN);
    cudaFuncSetAttribute(gemm_kernel<true>,  cudaFuncAttributeMaxDynamicSharedMemorySize, SMEM_DYN);

    split_x_kernel<<<(NN * 256 + 255) / 256, 256>>>(x0, x1);
    fold_kernel<<<96, 256>>>(Wk, bk, Ar, Mr);
    foldq_kernel<<<(2 * 6 * 256 * 256 + 255) / 256, 256>>>(Wk, bk, Wo);

    csr_zero_kernel<<<(2 * NP + 255) / 256, 256>>>();
    csr_hist_kernel<<<(EE + 255) / 256, 256>>>(e_dr + EE, e_rd + EE);
    csr_scan_kernel<<<2, 1024>>>();
    csr_scatter_kernel<<<(EE + 255) / 256, 256>>>(e_dr + EE, e_rd + EE);
    csr_sort_kernel<<<(2 * NP + 255) / 256, 256>>>(e_dr, e_rd);

    for (int l = 0; l < LL; l++) {
        const float* xres0 = (l == 0) ? x0 : gx;
        const float* xres1 = (l == 0) ? x1 : gx + NPF;
        float* Cout0 = (l == LL - 1) ? out : gx;
        float* Cout1 = (l == LL - 1) ? out + (size_t)NN * FF : gx + NPF;

        // kqv = x @ W_eff^T + b_eff  -> [ke|q|ve] fp32
        gemm_kernel<false><<<dim3(6, NP / 128, 2), 256, SMEM_DYN>>>(
            gxh, gxl,
            gWeh + (size_t)l * 2 * 768 * 256, gWel + (size_t)l * 2 * 768 * 256,
            gbe + (size_t)l * 2 * 768,
            gkqv, gkqv + (size_t)NP * 768, 768,
            nullptr, nullptr,
            (size_t)768 * 256, (size_t)768,
            nullptr, nullptr, nullptr);

        // attention -> gelu(agg) hi/lo fp16
        attn_kernel<<<(2 * NN * 32 + 255) / 256, 256>>>(pr + (size_t)l * 2 * HH);

        // x_next = relu( a*(gelu(agg) @ Wo^T + bo) + (1-a)*x ); also emits hi/lo(x_next)
        gemm_kernel<true><<<dim3(2, NP / 128, 2), 256, SMEM_DYN>>>(
            gaggh, gaggl,
            gWoh + (size_t)l * 2 * 256 * 256, gWol + (size_t)l * 2 * 256 * 256,
            bo + (size_t)l * 2 * FF,
            Cout0, Cout1, 256,
            gxh, gxl,
            (size_t)256 * 256, (size_t)256,
            xres0, xres1, sk + l * 2);
    }
}

// round 15
// speedup vs baseline: 1.1138x; 1.1138x over previous
#include <cuda_runtime.h>
#include <math.h>
#include <stdint.h>
#include <cuda_fp16.h>

#define NN 30000
#define NP 30080          // 235 * 128
#define EE 200000
#define FF 256
#define HH 8
#define DD 32
#define LL 3

typedef unsigned long long u64;

// tcgen05 path only on arch-specific ('a') compilation passes.
#if defined(__CUDA_ARCH__) && (defined(__CUDA_ARCH_FEAT_SM103_ALL) || defined(__CUDA_ARCH_FEAT_SM100_ALL) || defined(__CUDA_ARCH_SPECIFIC__))
#define TC_PATH 1
#else
#define TC_PATH 0
#endif

// ---------------- scratch (static device memory; no allocation) ----------------
__device__ float g_x  [2 * (size_t)NP * FF];        // padded rows never written -> stay 0
__device__ float g_kqv[2 * (size_t)NP * 3 * FF];    // ke | q | ve
__device__ float g_agg[2 * (size_t)NP * FF];        // padded rows stay 0 forever
__device__ float g_WeT[6 * (size_t)768 * 256];      // folded W_kqv, transposed: [lt][n][k]
__device__ float g_WoT[6 * (size_t)256 * 256];      // W_out transposed: [lt][n][k]
__device__ float g_be [6 * 3 * FF];

__device__ int g_deg[2 * NP];
__device__ int g_cur[2 * NP];
__device__ int g_off[2 * (NP + 1)];
__device__ int g_eid[2 * EE];
__device__ int g_srt[2 * EE];

__device__ __forceinline__ float gelu_exact(float x) {
    return 0.5f * x * (1.0f + erff(x * 0.70710678118654752440f));
}
__device__ __forceinline__ void ffma2(u64& d, u64 a, u64 b) {
    asm("fma.rn.f32x2 %0, %1, %2, %0;" : "+l"(d) : "l"(a), "l"(b));
}
__device__ __forceinline__ u64 dupf(float x) {
    u64 r; asm("mov.b64 %0, {%1, %1};" : "=l"(r) : "f"(x)); return r;
}
__device__ __forceinline__ uint32_t smem_u32(const void* p) {
    uint32_t a;
    asm("{ .reg .u64 t; cvta.to.shared.u64 t, %1; cvt.u32.u64 %0, t; }" : "=r"(a) : "l"(p));
    return a;
}

#if TC_PATH
// ---------------- tcgen05 helpers ----------------
__device__ __forceinline__ uint32_t swz(uint32_t b) { return b ^ ((b >> 3) & 0x70u); }
__device__ __forceinline__ u64 mkdesc(uint32_t addr) {
    const u64 base = (2ULL << 61) | (1ULL << 46) | (64ULL << 32) | (1ULL << 16);  // SW128, v1, SBO=64, LBO=1
    return base | ((u64)(addr >> 4) & 0x3FFFULL);
}
// idesc kind::f16 (fp16 in, fp32 acc): dF32(1<<4) | N128(16<<17) | M128(8<<24)
#define IDESC_F16 0x8200010u

__device__ __forceinline__ void mma_f16(uint32_t d, u64 ad, u64 bd, uint32_t en) {
    asm volatile(
        "{\n\t.reg .pred p;\n\t"
        "setp.ne.u32 p, %4, 0;\n\t"
        "tcgen05.mma.cta_group::1.kind::f16 [%0], %1, %2, %3, {%5, %5, %5, %5}, p;\n\t"
        "}"
        :: "r"(d), "l"(ad), "l"(bd), "r"(IDESC_F16), "r"(en), "r"(0u)
        : "memory");
}
__device__ __forceinline__ void tmem_alloc(uint32_t dst_smem, uint32_t ncols) {
    asm volatile("tcgen05.alloc.cta_group::1.sync.aligned.shared::cta.b32 [%0], %1;"
                 :: "r"(dst_smem), "r"(ncols) : "memory");
}
__device__ __forceinline__ void tmem_relinq() {
    asm volatile("tcgen05.relinquish_alloc_permit.cta_group::1.sync.aligned;");
}
__device__ __forceinline__ void tmem_dealloc(uint32_t base, uint32_t ncols) {
    asm volatile("tcgen05.dealloc.cta_group::1.sync.aligned.b32 %0, %1;" :: "r"(base), "r"(ncols));
}
__device__ __forceinline__ void mbar_init(uint32_t mbar, uint32_t cnt) {
    asm volatile("mbarrier.init.shared.b64 [%0], %1;" :: "r"(mbar), "r"(cnt) : "memory");
}
__device__ __forceinline__ void tc_commit(uint32_t mbar) {
    asm volatile("tcgen05.commit.cta_group::1.mbarrier::arrive::one.shared::cluster.b64 [%0];"
                 :: "r"(mbar) : "memory");
}
__device__ __forceinline__ void mbar_wait(uint32_t mbar, uint32_t parity) {
    uint32_t done = 0;
    do {
        asm volatile(
            "{\n\t.reg .pred p;\n\t"
            "mbarrier.try_wait.parity.acquire.cta.shared::cta.b64 p, [%1], %2, 0x989680;\n\t"
            "selp.b32 %0, 1, 0, p;\n\t}"
            : "=r"(done) : "r"(mbar), "r"(parity) : "memory");
    } while (!done);
}
__device__ __forceinline__ void fence_async_smem() {
    asm volatile("fence.proxy.async.shared::cta;" ::: "memory");
}
__device__ __forceinline__ void tc_fence_after() {
    asm volatile("tcgen05.fence::after_thread_sync;" ::: "memory");
}
__device__ __forceinline__ void tc_fence_before() {
    asm volatile("tcgen05.fence::before_thread_sync;" ::: "memory");
}
__device__ __forceinline__ void tc_wait_ld() {
    asm volatile("tcgen05.wait::ld.sync.aligned;" ::: "memory");
}
__device__ __forceinline__ void ldtm32(uint32_t (&r)[32], uint32_t tmem_addr) {
    asm volatile(
        "tcgen05.ld.sync.aligned.32x32b.x32.b32 "
        "{%0, %1, %2, %3, %4, %5, %6, %7, "
        " %8, %9, %10, %11, %12, %13, %14, %15, "
        " %16, %17, %18, %19, %20, %21, %22, %23, "
        " %24, %25, %26, %27, %28, %29, %30, %31}, [%32];"
        : "=r"(r[0]),  "=r"(r[1]),  "=r"(r[2]),  "=r"(r[3]),
          "=r"(r[4]),  "=r"(r[5]),  "=r"(r[6]),  "=r"(r[7]),
          "=r"(r[8]),  "=r"(r[9]),  "=r"(r[10]), "=r"(r[11]),
          "=r"(r[12]), "=r"(r[13]), "=r"(r[14]), "=r"(r[15]),
          "=r"(r[16]), "=r"(r[17]), "=r"(r[18]), "=r"(r[19]),
          "=r"(r[20]), "=r"(r[21]), "=r"(r[22]), "=r"(r[23]),
          "=r"(r[24]), "=r"(r[25]), "=r"(r[26]), "=r"(r[27]),
          "=r"(r[28]), "=r"(r[29]), "=r"(r[30]), "=r"(r[31])
        : "r"(tmem_addr));
}

// Load a [128 x 64] fp32 chunk (row stride 256, cols c0..c0+63) into hi/lo fp16 SW128
// tiles (128B rows). Row indices clamped to rowmax (clamped rows' values are unused).
__device__ __forceinline__ void load_chunk_f16(
    const float* __restrict__ src, int rowbase, int c0, int rowmax,
    uint32_t dHi, uint32_t dLo, bool dogelu, int tid)
{
#pragma unroll
    for (int pass = 0; pass < 8; pass++) {
        int row = pass * 16 + (tid >> 4);
        int gr  = min(rowbase + row, rowmax);
        int j4  = (tid & 15) * 4;
        float4 v = *(const float4*)(src + (size_t)gr * 256 + c0 + j4);
        if (dogelu) {
            v.x = gelu_exact(v.x); v.y = gelu_exact(v.y);
            v.z = gelu_exact(v.z); v.w = gelu_exact(v.w);
        }
        __half h0 = __float2half_rn(v.x), h1 = __float2half_rn(v.y);
        __half h2 = __float2half_rn(v.z), h3 = __float2half_rn(v.w);
        __half l0 = __float2half_rn(v.x - __half2float(h0));
        __half l1 = __float2half_rn(v.y - __half2float(h1));
        __half l2 = __float2half_rn(v.z - __half2float(h2));
        __half l3 = __float2half_rn(v.w - __half2float(h3));
        uint32_t hi01 = ((uint32_t)__half_as_ushort(h1) << 16) | __half_as_ushort(h0);
        uint32_t hi23 = ((uint32_t)__half_as_ushort(h3) << 16) | __half_as_ushort(h2);
        uint32_t lo01 = ((uint32_t)__half_as_ushort(l1) << 16) | __half_as_ushort(l0);
        uint32_t lo23 = ((uint32_t)__half_as_ushort(l3) << 16) | __half_as_ushort(l2);
        uint32_t sw = swz((uint32_t)row * 128u + (uint32_t)j4 * 2u);
        asm volatile("st.shared.v2.b32 [%0], {%1,%2};" :: "r"(dHi + sw), "r"(hi01), "r"(hi23) : "memory");
        asm volatile("st.shared.v2.b32 [%0], {%1,%2};" :: "r"(dLo + sw), "r"(lo01), "r"(lo23) : "memory");
    }
}
#endif  // TC_PATH

// ---------------- fold relation transforms into W_kqv (transposed output) ----------------
__global__ void __launch_bounds__(256) fold_kernel(
    const float* __restrict__ Wk, const float* __restrict__ bk,
    const float* __restrict__ Ar, const float* __restrict__ Mr)
{
    int bx = blockIdx.x;
    int lt = bx >> 4;
    int part = (bx >> 3) & 1;
    int h = bx & 7;
    const float* A = (part ? Mr : Ar) + (size_t)lt * HH * DD * DD + h * DD * DD;
    __shared__ float sA[DD * DD];
    int tid = threadIdx.x;
    for (int i = tid; i < DD * DD; i += 256) sA[i] = A[i];
    __syncthreads();
    int e = tid & 31;
    int rg = tid >> 5;
    int col = (part ? 512 : 0) + h * 32;
    for (int r = rg * 32; r < rg * 32 + 32; r++) {
        const float* w = Wk + (size_t)lt * 256 * 768 + (size_t)r * 768 + col;
        float acc = 0.0f;
#pragma unroll
        for (int d = 0; d < 32; d++) acc = fmaf(w[d], sA[d * 32 + e], acc);
        g_WeT[(size_t)lt * 768 * 256 + (size_t)(col + e) * 256 + r] = acc;
    }
    if (rg == 0) {
        const float* b = bk + (size_t)lt * 768 + col;
        float acc = 0.0f;
#pragma unroll
        for (int d = 0; d < 32; d++) acc = fmaf(b[d], sA[d * 32 + e], acc);
        g_be[lt * 768 + col + e] = acc;
    }
}

__global__ void foldq_kernel(const float* __restrict__ Wk, const float* __restrict__ bk,
                             const float* __restrict__ Wo) {
    int idx = blockIdx.x * 256 + threadIdx.x;
    if (idx < 6 * 256 * 256) {
        int lt = idx >> 16;
        int rem = idx & 65535;
        int c = rem >> 8;
        int r = rem & 255;
        g_WeT[(size_t)lt * 768 * 256 + (size_t)(256 + c) * 256 + r] =
            Wk[(size_t)lt * 256 * 768 + (size_t)r * 768 + 256 + c];
    } else if (idx < 2 * 6 * 256 * 256) {
        int i2 = idx - 6 * 256 * 256;
        int lt = i2 >> 16;
        int rem = i2 & 65535;
        int n = rem >> 8;
        int k = rem & 255;
        g_WoT[(size_t)lt * 65536 + (size_t)n * 256 + k] =
            Wo[(size_t)lt * 65536 + (size_t)k * 256 + n];
    }
    if (idx < 6 * 256) {
        int lt = idx >> 8, c = idx & 255;
        g_be[lt * 768 + 256 + c] = bk[lt * 768 + 256 + c];
    }
}

// ---------------- CSR build ----------------
__global__ void csr_zero_kernel() {
    int i = blockIdx.x * 256 + threadIdx.x;
    if (i < 2 * NP) { g_deg[i] = 0; g_cur[i] = 0; }
}
__global__ void csr_hist_kernel(const int* __restrict__ dst0, const int* __restrict__ dst1) {
    int e = blockIdx.x * 256 + threadIdx.x;
    if (e < EE) {
        atomicAdd(&g_deg[dst0[e]], 1);
        atomicAdd(&g_deg[NP + dst1[e]], 1);
    }
}
__global__ void __launch_bounds__(1024) csr_scan_kernel() {
    const int t = blockIdx.x;
    const int* deg = g_deg + t * NP;
    int* off = g_off + t * (NP + 1);
    const int tid = threadIdx.x;
    const int CH = 30;
    int base = tid * CH;
    int local[CH];
    int s = 0;
#pragma unroll
    for (int i = 0; i < CH; i++) {
        int idx = base + i;
        int v = (idx < NP) ? deg[idx] : 0;
        local[i] = s; s += v;
    }
    __shared__ int wsum[32];
    int lane = tid & 31, wid = tid >> 5;
    int ws = s;
#pragma unroll
    for (int o = 1; o < 32; o <<= 1) { int y = __shfl_up_sync(~0u, ws, o); if (lane >= o) ws += y; }
    if (lane == 31) wsum[wid] = ws;
    __syncthreads();
    if (wid == 0) {
        int v = wsum[lane];
#pragma unroll
        for (int o = 1; o < 32; o <<= 1) { int y = __shfl_up_sync(~0u, v, o); if (lane >= o) v += y; }
        wsum[lane] = v;
    }
    __syncthreads();
    int warpEx = (wid > 0) ? wsum[wid - 1] : 0;
    int ex = warpEx + ws - s;
#pragma unroll
    for (int i = 0; i < CH; i++) {
        int idx = base + i;
        if (idx < NP) off[idx] = ex + local[i];
    }
    if (tid == 1023) off[NP] = warpEx + ws;
}
__global__ void csr_scatter_kernel(const int* __restrict__ dst0, const int* __restrict__ dst1) {
    int e = blockIdx.x * 256 + threadIdx.x;
    if (e >= EE) return;
    int d0 = dst0[e];
    int p0 = g_off[d0] + atomicAdd(&g_cur[d0], 1);
    g_eid[p0] = e;
    int d1 = dst1[e];
    int p1 = g_off[(NP + 1) + d1] + atomicAdd(&g_cur[NP + d1], 1);
    g_eid[EE + p1] = e;
}
__global__ void csr_sort_kernel(const int* __restrict__ s0, const int* __restrict__ s1) {
    int idx = blockIdx.x * 256 + threadIdx.x;
    if (idx >= 2 * NP) return;
    int t = (idx >= NP) ? 1 : 0;
    int d = idx - t * NP;
    const int* off = g_off + t * (NP + 1);
    int b = off[d], e = off[d + 1];
    int* a = g_eid + t * EE;
    for (int i = b + 1; i < e; i++) {
        int key = a[i];
        int j = i - 1;
        while (j >= b && a[j] > key) { a[j + 1] = a[j]; j--; }
        a[j + 1] = key;
    }
    const int* sarr = t ? s1 : s0;
    int* o = g_srt + t * EE;
    for (int i = b; i < e; i++) o[i] = sarr[a[i]];
}

// ---------------- unified GEMM: C[M,Nc] = op(A)[M,256] @ BwT[Nc,256]^T + bias (+ epilogue) ----
// TC path: tcgen05 FP16 3x-split, K chunked by 64 (4 chunks), SINGLE 64KB stage ->
// 3 CTAs/SM; cross-CTA overlap hides load latency.
// Fallback: FFMA2 8x8-per-thread register blocking.
// Stores predicated to rows m < NN (padded rows never written anywhere).
#define SMEM_DYN (65536 + 1024)

template <bool GELU_A, bool EPI>
__global__ void __launch_bounds__(256) gemm_kernel(
    const float* __restrict__ A0, const float* __restrict__ A1,
    const float* __restrict__ BwT, const float* __restrict__ bias,
    float* __restrict__ C0, float* __restrict__ C1,
    int Nc, size_t sB_, size_t sb_,
    const float* __restrict__ xr0, const float* __restrict__ xr1,
    const float* __restrict__ skp)
{
    const int z = blockIdx.z;
    const float* A = z ? A1 : A0;
    float* C = z ? C1 : C0;
    const float* xres = z ? xr1 : xr0;
    BwT += (size_t)z * sB_; bias += (size_t)z * sb_;
    if (EPI) skp += z;

    extern __shared__ char dsm[];
    const int tid = threadIdx.x;
    const int m0 = blockIdx.y * 128;
    const int n0 = blockIdx.x * 128;

#if TC_PATH
    uint32_t st = (smem_u32(dsm) + 1023u) & ~1023u;   // Ahi | Alo | Bhi | Blo (16KB each)

    __shared__ uint32_t s_tmem;
    __shared__ __align__(8) u64 s_mbar;
    const int wid = tid >> 5;
    const int lane = tid & 31;

    if (wid == 0) { tmem_alloc(smem_u32(&s_tmem), 128); tmem_relinq(); }
    if (tid == 0) mbar_init(smem_u32(&s_mbar), 1);
    __syncthreads();
    uint32_t tmem;
    asm volatile("ld.shared.b32 %0, [%1];" : "=r"(tmem) : "r"(smem_u32(&s_tmem)));
    const uint32_t mbar = smem_u32(&s_mbar);

    const u64 dA = mkdesc(st), dAl = mkdesc(st + 16384);
    const u64 dB = mkdesc(st + 32768), dBl = mkdesc(st + 49152);

    for (int c = 0; c < 4; c++) {
        if (c > 0) mbar_wait(mbar, (uint32_t)((c - 1) & 1));
        load_chunk_f16(A,   m0, c * 64, NN - 1,     st,         st + 16384, GELU_A, tid);
        load_chunk_f16(BwT, n0, c * 64, 0x7FFFFFFF, st + 32768, st + 49152, false,  tid);
        __syncthreads();
        if (tid == 0) {
            fence_async_smem();
#pragma unroll
            for (int k = 0; k < 4; k++) {              // 4 k-steps of 16 within the 64-chunk
                uint32_t en = (c > 0 || k > 0) ? 1u : 0u;
                mma_f16(tmem, dA  + 2 * k, dB  + 2 * k, en);
                mma_f16(tmem, dAl + 2 * k, dB  + 2 * k, 1u);
                mma_f16(tmem, dA  + 2 * k, dBl + 2 * k, 1u);
            }
            tc_commit(mbar);
        }
    }
    mbar_wait(mbar, 1u);   // 4th commit completion
    tc_fence_after();

    float sAv = 0.0f;
    if (EPI) sAv = 1.0f / (1.0f + __expf(-skp[0]));
    if (wid < 4) {
        const int m = m0 + wid * 32 + lane;
        const int mr = min(m, NN - 1);                 // clamp for xres reads (unused if m>=NN)
#pragma unroll
        for (int g = 0; g < 4; g++) {
            uint32_t r[32];
            ldtm32(r, tmem + g * 32);
            tc_wait_ld();
            const int nb = n0 + g * 32;
            float ov[32];
#pragma unroll
            for (int j = 0; j < 32; j++) {
                float o = __uint_as_float(r[j]) + bias[nb + j];
                if (EPI) {
                    o = sAv * o + (1.0f - sAv) * xres[(size_t)mr * FF + nb + j];
                    o = fmaxf(o, 0.0f);
                }
                ov[j] = o;
            }
            if (m < NN) {
#pragma unroll
                for (int j = 0; j < 32; j += 4)
                    *(float4*)&C[(size_t)m * Nc + nb + j] = make_float4(ov[j], ov[j+1], ov[j+2], ov[j+3]);
            }
        }
        tc_fence_before();
    }
    __syncthreads();
    if (wid == 0) tmem_dealloc(tmem, 128);

#else   // ---------------- FFMA2 fallback ----------------
    float* As = (float*)dsm;
    float* Bs = (float*)dsm + 8 * 128;
    const int tx = tid & 15;
    const int ty = tid >> 4;

    u64 acc2[8][4];
#pragma unroll
    for (int i = 0; i < 8; i++)
#pragma unroll
        for (int j = 0; j < 4; j++) acc2[i][j] = 0ULL;

    const int ldRow = tid >> 1;
    const int ldK   = (tid & 1) * 4;
    const float* Ap = A + (size_t)min(m0 + ldRow, NN - 1) * 256 + ldK;
    const float* Bp = BwT + (size_t)(n0 + ldRow) * 256 + ldK;

    for (int k0 = 0; k0 < 256; k0 += 8) {
        float4 av = *(const float4*)(Ap + k0);
        float4 bv = *(const float4*)(Bp + k0);
        if (GELU_A) {
            av.x = gelu_exact(av.x); av.y = gelu_exact(av.y);
            av.z = gelu_exact(av.z); av.w = gelu_exact(av.w);
        }
        __syncthreads();
        As[(ldK + 0) * 128 + ldRow] = av.x; As[(ldK + 1) * 128 + ldRow] = av.y;
        As[(ldK + 2) * 128 + ldRow] = av.z; As[(ldK + 3) * 128 + ldRow] = av.w;
        Bs[(ldK + 0) * 128 + ldRow] = bv.x; Bs[(ldK + 1) * 128 + ldRow] = bv.y;
        Bs[(ldK + 2) * 128 + ldRow] = bv.z; Bs[(ldK + 3) * 128 + ldRow] = bv.w;
        __syncthreads();
#pragma unroll
        for (int k = 0; k < 8; k++) {
            float4 a0 = *(const float4*)&As[k * 128 + ty * 8];
            float4 a1 = *(const float4*)&As[k * 128 + ty * 8 + 4];
            const u64* bp = (const u64*)&Bs[k * 128 + tx * 8];
            u64 br0 = bp[0], br1 = bp[1], br2 = bp[2], br3 = bp[3];
            u64 ad[8];
            ad[0] = dupf(a0.x); ad[1] = dupf(a0.y); ad[2] = dupf(a0.z); ad[3] = dupf(a0.w);
            ad[4] = dupf(a1.x); ad[5] = dupf(a1.y); ad[6] = dupf(a1.z); ad[7] = dupf(a1.w);
#pragma unroll
            for (int i = 0; i < 8; i++) {
                ffma2(acc2[i][0], ad[i], br0);
                ffma2(acc2[i][1], ad[i], br1);
                ffma2(acc2[i][2], ad[i], br2);
                ffma2(acc2[i][3], ad[i], br3);
            }
        }
    }

    float sAv = 0.0f;
    if (EPI) sAv = 1.0f / (1.0f + __expf(-skp[0]));
#pragma unroll
    for (int i = 0; i < 8; i++) {
        int m = m0 + ty * 8 + i;
        int mr = min(m, NN - 1);
#pragma unroll
        for (int j = 0; j < 4; j++) {
            float2 v = *(float2*)&acc2[i][j];
            int n = n0 + tx * 8 + 2 * j;
            float o0 = v.x + bias[n];
            float o1 = v.y + bias[n + 1];
            if (EPI) {
                o0 = sAv * o0 + (1.0f - sAv) * xres[(size_t)mr * FF + n];
                o1 = sAv * o1 + (1.0f - sAv) * xres[(size_t)mr * FF + n + 1];
                o0 = fmaxf(o0, 0.0f);
                o1 = fmaxf(o1, 0.0f);
            }
            if (m < NN) {
                C[(size_t)m * Nc + n] = o0;
                C[(size_t)m * Nc + n + 1] = o1;
            }
        }
    }
#endif
}

// ---------------- fused edge attention: one warp per (dst type, dst node) ----------------
// Two independent online-softmax states over even/odd edges -> 2x load MLP + FMA ILP;
// states merged exactly at the end. Deterministic (fixed even/odd split).
__global__ void __launch_bounds__(256) attn_kernel(const float* __restrict__ pr_l)
{
    int w = (blockIdx.x * 256 + threadIdx.x) >> 5;
    if (w >= 2 * NN) return;
    const int dt = (w >= NN) ? 1 : 0;
    const int node = w - dt * NN;
    const int et = 1 - dt;
    const float* kqv_d = g_kqv + (size_t)dt * NP * 768;
    const float* kqv_s = g_kqv + (size_t)et * NP * 768;
    const int* off = g_off + et * (NP + 1);
    const int* srt = g_srt + et * EE;
    float* agg = g_agg + (size_t)dt * NP * FF;

    const int lane = threadIdx.x & 31;
    const int h = lane >> 2;
    const int co = h * 32 + (lane & 3) * 8;

    const float* qr = kqv_d + (size_t)node * 768 + 256 + co;
    float4 q0 = *(const float4*)qr;
    float4 q1 = *(const float4*)(qr + 4);
    const float ph = pr_l[et * HH + h] * 0.17677669529663688110f;

    // state 0 (even edges) and state 1 (odd edges)
    float mA = -INFINITY, zA = 0.0f;
    float4 aA0 = {0.f,0.f,0.f,0.f}, aA1 = {0.f,0.f,0.f,0.f};
    float mB = -INFINITY, zB = 0.0f;
    float4 aB0 = {0.f,0.f,0.f,0.f}, aB1 = {0.f,0.f,0.f,0.f};

    const int b = off[node], e2 = off[node + 1];
    int j = b;
    for (; j + 1 < e2; j += 2) {
        int s0 = srt[j];
        int s1 = srt[j + 1];
        const float* kr0 = kqv_s + (size_t)s0 * 768 + co;
        const float* kr1 = kqv_s + (size_t)s1 * 768 + co;
        // issue all 8 vector loads before any dependent math
        float4 k00 = *(const float4*)kr0;
        float4 k01 = *(const float4*)(kr0 + 4);
        float4 v00 = *(const float4*)(kr0 + 512);
        float4 v01 = *(const float4*)(kr0 + 516);
        float4 k10 = *(const float4*)kr1;
        float4 k11 = *(const float4*)(kr1 + 4);
        float4 v10 = *(const float4*)(kr1 + 512);
        float4 v11 = *(const float4*)(kr1 + 516);

        float d0 = q0.x*k00.x + q0.y*k00.y + q0.z*k00.z + q0.w*k00.w
                 + q1.x*k01.x + q1.y*k01.y + q1.z*k01.z + q1.w*k01.w;
        float d1 = q0.x*k10.x + q0.y*k10.y + q0.z*k10.z + q0.w*k10.w
                 + q1.x*k11.x + q1.y*k11.y + q1.z*k11.z + q1.w*k11.w;
        d0 += __shfl_xor_sync(0xffffffffu, d0, 1);
        d1 += __shfl_xor_sync(0xffffffffu, d1, 1);
        d0 += __shfl_xor_sync(0xffffffffu, d0, 2);
        d1 += __shfl_xor_sync(0xffffffffu, d1, 2);
        float sc0 = d0 * ph;
        float sc1 = d1 * ph;

        float nmA = fmaxf(mA, sc0);
        float nmB = fmaxf(mB, sc1);
        float scaleA = __expf(mA - nmA);
        float scaleB = __expf(mB - nmB);
        float eaA = __expf(sc0 - nmA);
        float eaB = __expf(sc1 - nmB);
        zA = zA * scaleA + eaA;
        zB = zB * scaleB + eaB;
        aA0.x = aA0.x*scaleA + eaA*v00.x;  aA0.y = aA0.y*scaleA + eaA*v00.y;
        aA0.z = aA0.z*scaleA + eaA*v00.z;  aA0.w = aA0.w*scaleA + eaA*v00.w;
        aA1.x = aA1.x*scaleA + eaA*v01.x;  aA1.y = aA1.y*scaleA + eaA*v01.y;
        aA1.z = aA1.z*scaleA + eaA*v01.z;  aA1.w = aA1.w*scaleA + eaA*v01.w;
        aB0.x = aB0.x*scaleB + eaB*v10.x;  aB0.y = aB0.y*scaleB + eaB*v10.y;
        aB0.z = aB0.z*scaleB + eaB*v10.z;  aB0.w = aB0.w*scaleB + eaB*v10.w;
        aB1.x = aB1.x*scaleB + eaB*v11.x;  aB1.y = aB1.y*scaleB + eaB*v11.y;
        aB1.z = aB1.z*scaleB + eaB*v11.z;  aB1.w = aB1.w*scaleB + eaB*v11.w;
        mA = nmA;
        mB = nmB;
    }
    if (j < e2) {                     // tail edge -> state A
        int s0 = srt[j];
        const float* kr0 = kqv_s + (size_t)s0 * 768 + co;
        float4 k00 = *(const float4*)kr0;
        float4 k01 = *(const float4*)(kr0 + 4);
        float4 v00 = *(const float4*)(kr0 + 512);
        float4 v01 = *(const float4*)(kr0 + 516);
        float d0 = q0.x*k00.x + q0.y*k00.y + q0.z*k00.z + q0.w*k00.w
                 + q1.x*k01.x + q1.y*k01.y + q1.z*k01.z + q1.w*k01.w;
        d0 += __shfl_xor_sync(0xffffffffu, d0, 1);
        d0 += __shfl_xor_sync(0xffffffffu, d0, 2);
        float sc0 = d0 * ph;
        float nmA = fmaxf(mA, sc0);
        float scaleA = __expf(mA - nmA);
        float eaA = __expf(sc0 - nmA);
        zA = zA * scaleA + eaA;
        aA0.x = aA0.x*scaleA + eaA*v00.x;  aA0.y = aA0.y*scaleA + eaA*v00.y;
        aA0.z = aA0.z*scaleA + eaA*v00.z;  aA0.w = aA0.w*scaleA + eaA*v00.w;
        aA1.x = aA1.x*scaleA + eaA*v01.x;  aA1.y = aA1.y*scaleA + eaA*v01.y;
        aA1.z = aA1.z*scaleA + eaA*v01.z;  aA1.w = aA1.w*scaleA + eaA*v01.w;
        mA = nmA;
    }

    // merge state B into state A (exact two-state softmax combine)
    if (mB > -INFINITY) {
        float nm = fmaxf(mA, mB);
        float eA = __expf(mA - nm);      // mA==-inf -> 0 (deg==1 handled: B empty anyway)
        float eB = __expf(mB - nm);
        zA = zA * eA + zB * eB;
        aA0.x = aA0.x*eA + aB0.x*eB;  aA0.y = aA0.y*eA + aB0.y*eB;
        aA0.z = aA0.z*eA + aB0.z*eB;  aA0.w = aA0.w*eA + aB0.w*eB;
        aA1.x = aA1.x*eA + aB1.x*eB;  aA1.y = aA1.y*eA + aB1.y*eB;
        aA1.z = aA1.z*eA + aB1.z*eB;  aA1.w = aA1.w*eA + aB1.w*eB;
    }

    float inv = (zA > 0.0f) ? 1.0f / zA : 0.0f;
    float* ar = agg + (size_t)node * 256 + co;
    *(float4*)ar       = make_float4(aA0.x * inv, aA0.y * inv, aA0.z * inv, aA0.w * inv);
    *(float4*)(ar + 4) = make_float4(aA1.x * inv, aA1.y * inv, aA1.z * inv, aA1.w * inv);
}

// ---------------- driver ----------------
extern "C" void kernel_launch(void* const* d_in, const int* in_sizes, int n_in,
                              void* d_out, int out_size)
{
    const float* x0 = (const float*)d_in[0];
    const float* x1 = (const float*)d_in[1];
    const int*   e_dr = (const int*)d_in[2];
    const int*   e_rd = (const int*)d_in[3];
    const float* Wk = (const float*)d_in[4];
    const float* bk = (const float*)d_in[5];
    const float* Ar = (const float*)d_in[6];
    const float* Mr = (const float*)d_in[7];
    const float* pr = (const float*)d_in[8];
    const float* Wo = (const float*)d_in[9];
    const float* bo = (const float*)d_in[10];
    const float* sk = (const float*)d_in[11];
    float* out = (float*)d_out;

    float *gx, *gkqv, *gagg, *gWeT, *gWoT, *gbe;
    cudaGetSymbolAddress((void**)&gx,   g_x);
    cudaGetSymbolAddress((void**)&gkqv, g_kqv);
    cudaGetSymbolAddress((void**)&gagg, g_agg);
    cudaGetSymbolAddress((void**)&gWeT, g_WeT);
    cudaGetSymbolAddress((void**)&gWoT, g_WoT);
    cudaGetSymbolAddress((void**)&gbe,  g_be);

    cudaFuncSetAttribute(gemm_kernel<false, false>, cudaFuncAttributeMaxDynamicSharedMemorySize, SMEM_DYN);
    cudaFuncSetAttribute(gemm_kernel<true, true>,  cudaFuncAttributeMaxDynamicSharedMemorySize, SMEM_DYN);

    fold_kernel<<<96, 256>>>(Wk, bk, Ar, Mr);
    foldq_kernel<<<(2 * 6 * 256 * 256 + 255) / 256, 256>>>(Wk, bk, Wo);

    csr_zero_kernel<<<(2 * NP + 255) / 256, 256>>>();
    csr_hist_kernel<<<(EE + 255) / 256, 256>>>(e_dr + EE, e_rd + EE);
    csr_scan_kernel<<<2, 1024>>>();
    csr_scatter_kernel<<<(EE + 255) / 256, 256>>>(e_dr + EE, e_rd + EE);
    csr_sort_kernel<<<(2 * NP + 255) / 256, 256>>>(e_dr, e_rd);

    for (int l = 0; l < LL; l++) {
        const float* Ain0 = (l == 0) ? x0 : gx;
        const float* Ain1 = (l == 0) ? x1 : gx + (size_t)NP * FF;
        float* Cout0 = (l == LL - 1) ? out : gx;
        float* Cout1 = (l == LL - 1) ? out + (size_t)NN * FF : gx + (size_t)NP * FF;

        // kqv = x @ W_eff^T + b_eff  -> [ke|q|ve]
        gemm_kernel<false, false><<<dim3(6, NP / 128, 2), 256, SMEM_DYN>>>(
            Ain0, Ain1,
            gWeT + (size_t)l * 2 * 768 * 256, gbe + (size_t)l * 2 * 768,
            gkqv, gkqv + (size_t)NP * 768,
            768, (size_t)768 * 256, (size_t)768,
            nullptr, nullptr, nullptr);

        attn_kernel<<<(2 * NN * 32 + 255) / 256, 256>>>(pr + (size_t)l * 2 * HH);

        // x_next = relu( a*(gelu(agg) @ Wo^T + bo) + (1-a)*x )
        gemm_kernel<true, true><<<dim3(2, NP / 128, 2), 256, SMEM_DYN>>>(
            gagg, gagg + (size_t)NP * FF,
            gWoT + (size_t)l * 2 * 256 * 256, bo + (size_t)l * 2 * FF,
            Cout0, Cout1,
            256, (size_t)256 * 256, (size_t)256,
            Ain0, Ain1, sk + l * 2);
    }
}

// round 17
// speedup vs baseline: 1.2524x; 1.1244x over previous
#include <cuda_runtime.h>
#include <math.h>
#include <stdint.h>
#include <cuda_fp16.h>

#define NN 30000
#define NP 30080          // 235 * 128
#define EE 200000
#define FF 256
#define HH 8
#define DD 32
#define LL 3

typedef unsigned long long u64;

// tcgen05 path only on arch-specific ('a') compilation passes.
#if defined(__CUDA_ARCH__) && (defined(__CUDA_ARCH_FEAT_SM103_ALL) || defined(__CUDA_ARCH_FEAT_SM100_ALL) || defined(__CUDA_ARCH_SPECIFIC__))
#define TC_PATH 1
#else
#define TC_PATH 0
#endif

// ---------------- scratch (static device memory; no allocation) ----------------
__device__ float  g_x  [2 * (size_t)NP * FF];       // fp32 x (residual + GEMM A); padded rows 0
__device__ float  g_qv [2 * (size_t)NP * 512];      // q (cols 0-255) | ve (cols 256-511), fp32
__device__ __half g_keh[2 * (size_t)NP * 256];      // ke, fp16 (edge-key working set -> L2)
__device__ float  g_agg[2 * (size_t)NP * FF];       // padded rows stay 0 forever
__device__ float  g_WeT[6 * (size_t)768 * 256];     // folded W_kqv, transposed: [lt][n][k]
__device__ float  g_WoT[6 * (size_t)256 * 256];     // W_out transposed: [lt][n][k]
__device__ float  g_be [6 * 3 * FF];

__device__ int g_deg[2 * NP];
__device__ int g_cur[2 * NP];
__device__ int g_off[2 * (NP + 1)];
__device__ int g_eid[2 * EE];
__device__ int g_srt[2 * EE];

__device__ __forceinline__ float gelu_exact(float x) {
    return 0.5f * x * (1.0f + erff(x * 0.70710678118654752440f));
}
__device__ __forceinline__ void ffma2(u64& d, u64 a, u64 b) {
    asm("fma.rn.f32x2 %0, %1, %2, %0;" : "+l"(d) : "l"(a), "l"(b));
}
__device__ __forceinline__ u64 dupf(float x) {
    u64 r; asm("mov.b64 %0, {%1, %1};" : "=l"(r) : "f"(x)); return r;
}
__device__ __forceinline__ uint32_t smem_u32(const void* p) {
    uint32_t a;
    asm("{ .reg .u64 t; cvta.to.shared.u64 t, %1; cvt.u32.u64 %0, t; }" : "=r"(a) : "l"(p));
    return a;
}
__device__ __forceinline__ uint32_t packh2(float a, float b) {
    __half2 p = __halves2half2(__float2half_rn(a), __float2half_rn(b));
    return *(uint32_t*)&p;
}

#if TC_PATH
// ---------------- tcgen05 helpers ----------------
__device__ __forceinline__ uint32_t swz(uint32_t b) { return b ^ ((b >> 3) & 0x70u); }
__device__ __forceinline__ u64 mkdesc(uint32_t addr) {
    const u64 base = (2ULL << 61) | (1ULL << 46) | (64ULL << 32) | (1ULL << 16);  // SW128, v1, SBO=64, LBO=1
    return base | ((u64)(addr >> 4) & 0x3FFFULL);
}
// idesc kind::f16 (fp16 in, fp32 acc): dF32(1<<4) | N128(16<<17) | M128(8<<24)
#define IDESC_F16 0x8200010u

__device__ __forceinline__ void mma_f16(uint32_t d, u64 ad, u64 bd, uint32_t en) {
    asm volatile(
        "{\n\t.reg .pred p;\n\t"
        "setp.ne.u32 p, %4, 0;\n\t"
        "tcgen05.mma.cta_group::1.kind::f16 [%0], %1, %2, %3, {%5, %5, %5, %5}, p;\n\t"
        "}"
        :: "r"(d), "l"(ad), "l"(bd), "r"(IDESC_F16), "r"(en), "r"(0u)
        : "memory");
}
__device__ __forceinline__ void tmem_alloc(uint32_t dst_smem, uint32_t ncols) {
    asm volatile("tcgen05.alloc.cta_group::1.sync.aligned.shared::cta.b32 [%0], %1;"
                 :: "r"(dst_smem), "r"(ncols) : "memory");
}
__device__ __forceinline__ void tmem_relinq() {
    asm volatile("tcgen05.relinquish_alloc_permit.cta_group::1.sync.aligned;");
}
__device__ __forceinline__ void tmem_dealloc(uint32_t base, uint32_t ncols) {
    asm volatile("tcgen05.dealloc.cta_group::1.sync.aligned.b32 %0, %1;" :: "r"(base), "r"(ncols));
}
__device__ __forceinline__ void mbar_init(uint32_t mbar, uint32_t cnt) {
    asm volatile("mbarrier.init.shared.b64 [%0], %1;" :: "r"(mbar), "r"(cnt) : "memory");
}
__device__ __forceinline__ void tc_commit(uint32_t mbar) {
    asm volatile("tcgen05.commit.cta_group::1.mbarrier::arrive::one.shared::cluster.b64 [%0];"
                 :: "r"(mbar) : "memory");
}
__device__ __forceinline__ void mbar_wait(uint32_t mbar, uint32_t parity) {
    uint32_t done = 0;
    do {
        asm volatile(
            "{\n\t.reg .pred p;\n\t"
            "mbarrier.try_wait.parity.acquire.cta.shared::cta.b64 p, [%1], %2, 0x989680;\n\t"
            "selp.b32 %0, 1, 0, p;\n\t}"
            : "=r"(done) : "r"(mbar), "r"(parity) : "memory");
    } while (!done);
}
__device__ __forceinline__ void fence_async_smem() {
    asm volatile("fence.proxy.async.shared::cta;" ::: "memory");
}
__device__ __forceinline__ void tc_fence_after() {
    asm volatile("tcgen05.fence::after_thread_sync;" ::: "memory");
}
__device__ __forceinline__ void tc_fence_before() {
    asm volatile("tcgen05.fence::before_thread_sync;" ::: "memory");
}
__device__ __forceinline__ void tc_wait_ld() {
    asm volatile("tcgen05.wait::ld.sync.aligned;" ::: "memory");
}
__device__ __forceinline__ void ldtm32(uint32_t (&r)[32], uint32_t tmem_addr) {
    asm volatile(
        "tcgen05.ld.sync.aligned.32x32b.x32.b32 "
        "{%0, %1, %2, %3, %4, %5, %6, %7, "
        " %8, %9, %10, %11, %12, %13, %14, %15, "
        " %16, %17, %18, %19, %20, %21, %22, %23, "
        " %24, %25, %26, %27, %28, %29, %30, %31}, [%32];"
        : "=r"(r[0]),  "=r"(r[1]),  "=r"(r[2]),  "=r"(r[3]),
          "=r"(r[4]),  "=r"(r[5]),  "=r"(r[6]),  "=r"(r[7]),
          "=r"(r[8]),  "=r"(r[9]),  "=r"(r[10]), "=r"(r[11]),
          "=r"(r[12]), "=r"(r[13]), "=r"(r[14]), "=r"(r[15]),
          "=r"(r[16]), "=r"(r[17]), "=r"(r[18]), "=r"(r[19]),
          "=r"(r[20]), "=r"(r[21]), "=r"(r[22]), "=r"(r[23]),
          "=r"(r[24]), "=r"(r[25]), "=r"(r[26]), "=r"(r[27]),
          "=r"(r[28]), "=r"(r[29]), "=r"(r[30]), "=r"(r[31])
        : "r"(tmem_addr));
}

// Load a [128 x 64] fp32 chunk (row stride 256, cols c0..c0+63) into hi/lo fp16 SW128
// tiles (128B rows). Row indices clamped to rowmax (clamped rows' values are unused).
__device__ __forceinline__ void load_chunk_f16(
    const float* __restrict__ src, int rowbase, int c0, int rowmax,
    uint32_t dHi, uint32_t dLo, bool dogelu, int tid)
{
#pragma unroll
    for (int pass = 0; pass < 8; pass++) {
        int row = pass * 16 + (tid >> 4);
        int gr  = min(rowbase + row, rowmax);
        int j4  = (tid & 15) * 4;
        float4 v = *(const float4*)(src + (size_t)gr * 256 + c0 + j4);
        if (dogelu) {
            v.x = gelu_exact(v.x); v.y = gelu_exact(v.y);
            v.z = gelu_exact(v.z); v.w = gelu_exact(v.w);
        }
        __half h0 = __float2half_rn(v.x), h1 = __float2half_rn(v.y);
        __half h2 = __float2half_rn(v.z), h3 = __float2half_rn(v.w);
        __half l0 = __float2half_rn(v.x - __half2float(h0));
        __half l1 = __float2half_rn(v.y - __half2float(h1));
        __half l2 = __float2half_rn(v.z - __half2float(h2));
        __half l3 = __float2half_rn(v.w - __half2float(h3));
        uint32_t hi01 = ((uint32_t)__half_as_ushort(h1) << 16) | __half_as_ushort(h0);
        uint32_t hi23 = ((uint32_t)__half_as_ushort(h3) << 16) | __half_as_ushort(h2);
        uint32_t lo01 = ((uint32_t)__half_as_ushort(l1) << 16) | __half_as_ushort(l0);
        uint32_t lo23 = ((uint32_t)__half_as_ushort(l3) << 16) | __half_as_ushort(l2);
        uint32_t sw = swz((uint32_t)row * 128u + (uint32_t)j4 * 2u);
        asm volatile("st.shared.v2.b32 [%0], {%1,%2};" :: "r"(dHi + sw), "r"(hi01), "r"(hi23) : "memory");
        asm volatile("st.shared.v2.b32 [%0], {%1,%2};" :: "r"(dLo + sw), "r"(lo01), "r"(lo23) : "memory");
    }
}
#endif  // TC_PATH

// ---------------- fold relation transforms into W_kqv (transposed output) ----------------
__global__ void __launch_bounds__(256) fold_kernel(
    const float* __restrict__ Wk, const float* __restrict__ bk,
    const float* __restrict__ Ar, const float* __restrict__ Mr)
{
    int bx = blockIdx.x;
    int lt = bx >> 4;
    int part = (bx >> 3) & 1;
    int h = bx & 7;
    const float* A = (part ? Mr : Ar) + (size_t)lt * HH * DD * DD + h * DD * DD;
    __shared__ float sA[DD * DD];
    int tid = threadIdx.x;
    for (int i = tid; i < DD * DD; i += 256) sA[i] = A[i];
    __syncthreads();
    int e = tid & 31;
    int rg = tid >> 5;
    int col = (part ? 512 : 0) + h * 32;
    for (int r = rg * 32; r < rg * 32 + 32; r++) {
        const float* w = Wk + (size_t)lt * 256 * 768 + (size_t)r * 768 + col;
        float acc = 0.0f;
#pragma unroll
        for (int d = 0; d < 32; d++) acc = fmaf(w[d], sA[d * 32 + e], acc);
        g_WeT[(size_t)lt * 768 * 256 + (size_t)(col + e) * 256 + r] = acc;
    }
    if (rg == 0) {
        const float* b = bk + (size_t)lt * 768 + col;
        float acc = 0.0f;
#pragma unroll
        for (int d = 0; d < 32; d++) acc = fmaf(b[d], sA[d * 32 + e], acc);
        g_be[lt * 768 + col + e] = acc;
    }
}

__global__ void foldq_kernel(const float* __restrict__ Wk, const float* __restrict__ bk,
                             const float* __restrict__ Wo) {
    int idx = blockIdx.x * 256 + threadIdx.x;
    if (idx < 6 * 256 * 256) {
        int lt = idx >> 16;
        int rem = idx & 65535;
        int c = rem >> 8;
        int r = rem & 255;
        g_WeT[(size_t)lt * 768 * 256 + (size_t)(256 + c) * 256 + r] =
            Wk[(size_t)lt * 256 * 768 + (size_t)r * 768 + 256 + c];
    } else if (idx < 2 * 6 * 256 * 256) {
        int i2 = idx - 6 * 256 * 256;
        int lt = i2 >> 16;
        int rem = i2 & 65535;
        int n = rem >> 8;
        int k = rem & 255;
        g_WoT[(size_t)lt * 65536 + (size_t)n * 256 + k] =
            Wo[(size_t)lt * 65536 + (size_t)k * 256 + n];
    }
    if (idx < 6 * 256) {
        int lt = idx >> 8, c = idx & 255;
        g_be[lt * 768 + 256 + c] = bk[lt * 768 + 256 + c];
    }
}

// ---------------- CSR build ----------------
__global__ void csr_zero_kernel() {
    int i = blockIdx.x * 256 + threadIdx.x;
    if (i < 2 * NP) { g_deg[i] = 0; g_cur[i] = 0; }
}
__global__ void csr_hist_kernel(const int* __restrict__ dst0, const int* __restrict__ dst1) {
    int e = blockIdx.x * 256 + threadIdx.x;
    if (e < EE) {
        atomicAdd(&g_deg[dst0[e]], 1);
        atomicAdd(&g_deg[NP + dst1[e]], 1);
    }
}
__global__ void __launch_bounds__(1024) csr_scan_kernel() {
    const int t = blockIdx.x;
    const int* deg = g_deg + t * NP;
    int* off = g_off + t * (NP + 1);
    const int tid = threadIdx.x;
    const int CH = 30;
    int base = tid * CH;
    int local[CH];
    int s = 0;
#pragma unroll
    for (int i = 0; i < CH; i++) {
        int idx = base + i;
        int v = (idx < NP) ? deg[idx] : 0;
        local[i] = s; s += v;
    }
    __shared__ int wsum[32];
    int lane = tid & 31, wid = tid >> 5;
    int ws = s;
#pragma unroll
    for (int o = 1; o < 32; o <<= 1) { int y = __shfl_up_sync(~0u, ws, o); if (lane >= o) ws += y; }
    if (lane == 31) wsum[wid] = ws;
    __syncthreads();
    if (wid == 0) {
        int v = wsum[lane];
#pragma unroll
        for (int o = 1; o < 32; o <<= 1) { int y = __shfl_up_sync(~0u, v, o); if (lane >= o) v += y; }
        wsum[lane] = v;
    }
    __syncthreads();
    int warpEx = (wid > 0) ? wsum[wid - 1] : 0;
    int ex = warpEx + ws - s;
#pragma unroll
    for (int i = 0; i < CH; i++) {
        int idx = base + i;
        if (idx < NP) off[idx] = ex + local[i];
    }
    if (tid == 1023) off[NP] = warpEx + ws;
}
__global__ void csr_scatter_kernel(const int* __restrict__ dst0, const int* __restrict__ dst1) {
    int e = blockIdx.x * 256 + threadIdx.x;
    if (e >= EE) return;
    int d0 = dst0[e];
    int p0 = g_off[d0] + atomicAdd(&g_cur[d0], 1);
    g_eid[p0] = e;
    int d1 = dst1[e];
    int p1 = g_off[(NP + 1) + d1] + atomicAdd(&g_cur[NP + d1], 1);
    g_eid[EE + p1] = e;
}
__global__ void csr_sort_kernel(const int* __restrict__ s0, const int* __restrict__ s1) {
    int idx = blockIdx.x * 256 + threadIdx.x;
    if (idx >= 2 * NP) return;
    int t = (idx >= NP) ? 1 : 0;
    int d = idx - t * NP;
    const int* off = g_off + t * (NP + 1);
    int b = off[d], e = off[d + 1];
    int* a = g_eid + t * EE;
    for (int i = b + 1; i < e; i++) {
        int key = a[i];
        int j = i - 1;
        while (j >= b && a[j] > key) { a[j + 1] = a[j]; j--; }
        a[j + 1] = key;
    }
    const int* sarr = t ? s1 : s0;
    int* o = g_srt + t * EE;
    for (int i = b; i < e; i++) o[i] = sarr[a[i]];
}

// ---------------- unified GEMM: C = op(A)[M,256] @ BwT[Nc,256]^T + bias (+ epilogue) ----
// KQV mode: column blocks 0-1 -> ke as fp16 into Kh (stride 256 halves);
//           blocks 2-5 -> q|ve fp32 into QV (stride 512, col = n - 256).
// EPI mode: skip/relu epilogue into C (stride 256).
#define SMEM_DYN (65536 + 1024)

template <bool KQV, bool EPI>
__global__ void __launch_bounds__(256) gemm_kernel(
    const float* __restrict__ A0, const float* __restrict__ A1,
    const float* __restrict__ BwT, const float* __restrict__ bias,
    float* __restrict__ C0, float* __restrict__ C1,   // EPI: x/out. KQV: qv (stride 512)
    __half* __restrict__ KhB,                         // KQV: keh base (z offset applied)
    size_t sB_, size_t sb_,
    const float* __restrict__ xr0, const float* __restrict__ xr1,
    const float* __restrict__ skp)
{
    const int z = blockIdx.z;
    const float* A = z ? A1 : A0;
    float* C = z ? C1 : C0;
    const float* xres = z ? xr1 : xr0;
    __half* Kh = KhB + (size_t)z * NP * 256;
    BwT += (size_t)z * sB_; bias += (size_t)z * sb_;
    if (EPI) skp += z;

    extern __shared__ char dsm[];
    const int tid = threadIdx.x;
    const int m0 = blockIdx.y * 128;
    const int n0 = blockIdx.x * 128;

#if TC_PATH
    uint32_t st = (smem_u32(dsm) + 1023u) & ~1023u;   // Ahi | Alo | Bhi | Blo (16KB each)

    __shared__ uint32_t s_tmem;
    __shared__ __align__(8) u64 s_mbar;
    const int wid = tid >> 5;
    const int lane = tid & 31;

    if (wid == 0) { tmem_alloc(smem_u32(&s_tmem), 128); tmem_relinq(); }
    if (tid == 0) mbar_init(smem_u32(&s_mbar), 1);
    __syncthreads();
    uint32_t tmem;
    asm volatile("ld.shared.b32 %0, [%1];" : "=r"(tmem) : "r"(smem_u32(&s_tmem)));
    const uint32_t mbar = smem_u32(&s_mbar);

    const u64 dA = mkdesc(st), dAl = mkdesc(st + 16384);
    const u64 dB = mkdesc(st + 32768), dBl = mkdesc(st + 49152);

    for (int c = 0; c < 4; c++) {
        if (c > 0) mbar_wait(mbar, (uint32_t)((c - 1) & 1));
        load_chunk_f16(A,   m0, c * 64, NN - 1,     st,         st + 16384, EPI, tid);
        load_chunk_f16(BwT, n0, c * 64, 0x7FFFFFFF, st + 32768, st + 49152, false,  tid);
        __syncthreads();
        if (tid == 0) {
            fence_async_smem();
#pragma unroll
            for (int k = 0; k < 4; k++) {
                uint32_t en = (c > 0 || k > 0) ? 1u : 0u;
                mma_f16(tmem, dA  + 2 * k, dB  + 2 * k, en);
                mma_f16(tmem, dAl + 2 * k, dB  + 2 * k, 1u);
                mma_f16(tmem, dA  + 2 * k, dBl + 2 * k, 1u);
            }
            tc_commit(mbar);
        }
    }
    mbar_wait(mbar, 1u);
    tc_fence_after();

    float sAv = 0.0f;
    if (EPI) sAv = 1.0f / (1.0f + __expf(-skp[0]));
    if (wid < 4) {
        const int m = m0 + wid * 32 + lane;
        const int mr = min(m, NN - 1);
#pragma unroll
        for (int g = 0; g < 4; g++) {
            uint32_t r[32];
            ldtm32(r, tmem + g * 32);
            tc_wait_ld();
            const int nb = n0 + g * 32;
            float ov[32];
#pragma unroll
            for (int j = 0; j < 32; j++) {
                float o = __uint_as_float(r[j]) + bias[nb + j];
                if (EPI) {
                    o = sAv * o + (1.0f - sAv) * xres[(size_t)mr * FF + nb + j];
                    o = fmaxf(o, 0.0f);
                }
                ov[j] = o;
            }
            if (m < NN) {
                if (KQV && n0 < 256) {
                    // ke -> fp16 packed (32 halves = 2x uint4)
#pragma unroll
                    for (int j = 0; j < 32; j += 8) {
                        uint4 vh = make_uint4(packh2(ov[j], ov[j+1]), packh2(ov[j+2], ov[j+3]),
                                              packh2(ov[j+4], ov[j+5]), packh2(ov[j+6], ov[j+7]));
                        *(uint4*)&Kh[(size_t)m * 256 + nb + j] = vh;
                    }
                } else if (KQV) {
                    // q|ve -> fp32, qv stride 512, col = nb - 256
#pragma unroll
                    for (int j = 0; j < 32; j += 4)
                        *(float4*)&C[(size_t)m * 512 + (nb - 256) + j] =
                            make_float4(ov[j], ov[j+1], ov[j+2], ov[j+3]);
                } else {
#pragma unroll
                    for (int j = 0; j < 32; j += 4)
                        *(float4*)&C[(size_t)m * 256 + nb + j] =
                            make_float4(ov[j], ov[j+1], ov[j+2], ov[j+3]);
                }
            }
        }
        tc_fence_before();
    }
    __syncthreads();
    if (wid == 0) tmem_dealloc(tmem, 128);

#else   // ---------------- FFMA2 fallback ----------------
    float* As = (float*)dsm;
    float* Bs = (float*)dsm + 8 * 128;
    const int tx = tid & 15;
    const int ty = tid >> 4;

    u64 acc2[8][4];
#pragma unroll
    for (int i = 0; i < 8; i++)
#pragma unroll
        for (int j = 0; j < 4; j++) acc2[i][j] = 0ULL;

    const int ldRow = tid >> 1;
    const int ldK   = (tid & 1) * 4;
    const float* Ap = A + (size_t)min(m0 + ldRow, NN - 1) * 256 + ldK;
    const float* Bp = BwT + (size_t)(n0 + ldRow) * 256 + ldK;

    for (int k0 = 0; k0 < 256; k0 += 8) {
        float4 av = *(const float4*)(Ap + k0);
        float4 bv = *(const float4*)(Bp + k0);
        if (EPI) {
            av.x = gelu_exact(av.x); av.y = gelu_exact(av.y);
            av.z = gelu_exact(av.z); av.w = gelu_exact(av.w);
        }
        __syncthreads();
        As[(ldK + 0) * 128 + ldRow] = av.x; As[(ldK + 1) * 128 + ldRow] = av.y;
        As[(ldK + 2) * 128 + ldRow] = av.z; As[(ldK + 3) * 128 + ldRow] = av.w;
        Bs[(ldK + 0) * 128 + ldRow] = bv.x; Bs[(ldK + 1) * 128 + ldRow] = bv.y;
        Bs[(ldK + 2) * 128 + ldRow] = bv.z; Bs[(ldK + 3) * 128 + ldRow] = bv.w;
        __syncthreads();
#pragma unroll
        for (int k = 0; k < 8; k++) {
            float4 a0 = *(const float4*)&As[k * 128 + ty * 8];
            float4 a1 = *(const float4*)&As[k * 128 + ty * 8 + 4];
            const u64* bp = (const u64*)&Bs[k * 128 + tx * 8];
            u64 br0 = bp[0], br1 = bp[1], br2 = bp[2], br3 = bp[3];
            u64 ad[8];
            ad[0] = dupf(a0.x); ad[1] = dupf(a0.y); ad[2] = dupf(a0.z); ad[3] = dupf(a0.w);
            ad[4] = dupf(a1.x); ad[5] = dupf(a1.y); ad[6] = dupf(a1.z); ad[7] = dupf(a1.w);
#pragma unroll
            for (int i = 0; i < 8; i++) {
                ffma2(acc2[i][0], ad[i], br0);
                ffma2(acc2[i][1], ad[i], br1);
                ffma2(acc2[i][2], ad[i], br2);
                ffma2(acc2[i][3], ad[i], br3);
            }
        }
    }

    float sAv = 0.0f;
    if (EPI) sAv = 1.0f / (1.0f + __expf(-skp[0]));
#pragma unroll
    for (int i = 0; i < 8; i++) {
        int m = m0 + ty * 8 + i;
        int mr = min(m, NN - 1);
#pragma unroll
        for (int j = 0; j < 4; j++) {
            float2 v = *(float2*)&acc2[i][j];
            int n = n0 + tx * 8 + 2 * j;
            float o0 = v.x + bias[n];
            float o1 = v.y + bias[n + 1];
            if (EPI) {
                o0 = sAv * o0 + (1.0f - sAv) * xres[(size_t)mr * FF + n];
                o1 = sAv * o1 + (1.0f - sAv) * xres[(size_t)mr * FF + n + 1];
                o0 = fmaxf(o0, 0.0f);
                o1 = fmaxf(o1, 0.0f);
            }
            if (m < NN) {
                if (KQV && n0 < 256) {
                    Kh[(size_t)m * 256 + n]     = __float2half_rn(o0);
                    Kh[(size_t)m * 256 + n + 1] = __float2half_rn(o1);
                } else if (KQV) {
                    C[(size_t)m * 512 + (n - 256)]     = o0;
                    C[(size_t)m * 512 + (n - 256) + 1] = o1;
                } else {
                    C[(size_t)m * 256 + n]     = o0;
                    C[(size_t)m * 256 + n + 1] = o1;
                }
            }
        }
    }
#endif
}

// ---------------- fused edge attention: one warp per (dst type, dst node) ----------------
// ke fp16 (stride 256), q|ve fp32 (stride 512). Dual-state online softmax (even/odd).
__global__ void __launch_bounds__(256) attn_kernel(const float* __restrict__ pr_l)
{
    int w = (blockIdx.x * 256 + threadIdx.x) >> 5;
    if (w >= 2 * NN) return;
    const int dt = (w >= NN) ? 1 : 0;
    const int node = w - dt * NN;
    const int et = 1 - dt;
    const float*  qv_d  = g_qv  + (size_t)dt * NP * 512;
    const float*  qv_s  = g_qv  + (size_t)et * NP * 512;
    const __half* keh_s = g_keh + (size_t)et * NP * 256;
    const int* off = g_off + et * (NP + 1);
    const int* srt = g_srt + et * EE;
    float* agg = g_agg + (size_t)dt * NP * FF;

    const int lane = threadIdx.x & 31;
    const int h = lane >> 2;
    const int co = h * 32 + (lane & 3) * 8;

    const float* qr = qv_d + (size_t)node * 512 + co;
    float4 q0 = *(const float4*)qr;
    float4 q1 = *(const float4*)(qr + 4);
    const float ph = pr_l[et * HH + h] * 0.17677669529663688110f;

    float mA = -INFINITY, zA = 0.0f;
    float4 aA0 = {0.f,0.f,0.f,0.f}, aA1 = {0.f,0.f,0.f,0.f};
    float mB = -INFINITY, zB = 0.0f;
    float4 aB0 = {0.f,0.f,0.f,0.f}, aB1 = {0.f,0.f,0.f,0.f};

    const int b = off[node], e2 = off[node + 1];
    int j = b;
    for (; j + 1 < e2; j += 2) {
        int s0 = srt[j];
        int s1 = srt[j + 1];
        const __half* kh0 = keh_s + (size_t)s0 * 256 + co;
        const __half* kh1 = keh_s + (size_t)s1 * 256 + co;
        const float*  vr0 = qv_s + (size_t)s0 * 512 + 256 + co;
        const float*  vr1 = qv_s + (size_t)s1 * 512 + 256 + co;
        uint4 kp0 = *(const uint4*)kh0;           // 8 halves
        uint4 kp1 = *(const uint4*)kh1;
        float4 v00 = *(const float4*)vr0;
        float4 v01 = *(const float4*)(vr0 + 4);
        float4 v10 = *(const float4*)vr1;
        float4 v11 = *(const float4*)(vr1 + 4);

        const __half2* h0p = (const __half2*)&kp0;
        const __half2* h1p = (const __half2*)&kp1;
        float2 ka = __half22float2(h0p[0]), kb = __half22float2(h0p[1]);
        float2 kc = __half22float2(h0p[2]), kd = __half22float2(h0p[3]);
        float2 la = __half22float2(h1p[0]), lb = __half22float2(h1p[1]);
        float2 lc = __half22float2(h1p[2]), ld = __half22float2(h1p[3]);

        float d0 = q0.x*ka.x + q0.y*ka.y + q0.z*kb.x + q0.w*kb.y
                 + q1.x*kc.x + q1.y*kc.y + q1.z*kd.x + q1.w*kd.y;
        float d1 = q0.x*la.x + q0.y*la.y + q0.z*lb.x + q0.w*lb.y
                 + q1.x*lc.x + q1.y*lc.y + q1.z*ld.x + q1.w*ld.y;
        d0 += __shfl_xor_sync(0xffffffffu, d0, 1);
        d1 += __shfl_xor_sync(0xffffffffu, d1, 1);
        d0 += __shfl_xor_sync(0xffffffffu, d0, 2);
        d1 += __shfl_xor_sync(0xffffffffu, d1, 2);
        float sc0 = d0 * ph;
        float sc1 = d1 * ph;

        float nmA = fmaxf(mA, sc0);
        float nmB = fmaxf(mB, sc1);
        float scaleA = __expf(mA - nmA);
        float scaleB = __expf(mB - nmB);
        float eaA = __expf(sc0 - nmA);
        float eaB = __expf(sc1 - nmB);
        zA = zA * scaleA + eaA;
        zB = zB * scaleB + eaB;
        aA0.x = aA0.x*scaleA + eaA*v00.x;  aA0.y = aA0.y*scaleA + eaA*v00.y;
        aA0.z = aA0.z*scaleA + eaA*v00.z;  aA0.w = aA0.w*scaleA + eaA*v00.w;
        aA1.x = aA1.x*scaleA + eaA*v01.x;  aA1.y = aA1.y*scaleA + eaA*v01.y;
        aA1.z = aA1.z*scaleA + eaA*v01.z;  aA1.w = aA1.w*scaleA + eaA*v01.w;
        aB0.x = aB0.x*scaleB + eaB*v10.x;  aB0.y = aB0.y*scaleB + eaB*v10.y;
        aB0.z = aB0.z*scaleB + eaB*v10.z;  aB0.w = aB0.w*scaleB + eaB*v10.w;
        aB1.x = aB1.x*scaleB + eaB*v11.x;  aB1.y = aB1.y*scaleB + eaB*v11.y;
        aB1.z = aB1.z*scaleB + eaB*v11.z;  aB1.w = aB1.w*scaleB + eaB*v11.w;
        mA = nmA;
        mB = nmB;
    }
    if (j < e2) {                     // tail edge -> state A
        int s0 = srt[j];
        const __half* kh0 = keh_s + (size_t)s0 * 256 + co;
        const float*  vr0 = qv_s + (size_t)s0 * 512 + 256 + co;
        uint4 kp0 = *(const uint4*)kh0;
        float4 v00 = *(const float4*)vr0;
        float4 v01 = *(const float4*)(vr0 + 4);
        const __half2* h0p = (const __half2*)&kp0;
        float2 ka = __half22float2(h0p[0]), kb = __half22float2(h0p[1]);
        float2 kc = __half22float2(h0p[2]), kd = __half22float2(h0p[3]);
        float d0 = q0.x*ka.x + q0.y*ka.y + q0.z*kb.x + q0.w*kb.y
                 + q1.x*kc.x + q1.y*kc.y + q1.z*kd.x + q1.w*kd.y;
        d0 += __shfl_xor_sync(0xffffffffu, d0, 1);
        d0 += __shfl_xor_sync(0xffffffffu, d0, 2);
        float sc0 = d0 * ph;
        float nmA = fmaxf(mA, sc0);
        float scaleA = __expf(mA - nmA);
        float eaA = __expf(sc0 - nmA);
        zA = zA * scaleA + eaA;
        aA0.x = aA0.x*scaleA + eaA*v00.x;  aA0.y = aA0.y*scaleA + eaA*v00.y;
        aA0.z = aA0.z*scaleA + eaA*v00.z;  aA0.w = aA0.w*scaleA + eaA*v00.w;
        aA1.x = aA1.x*scaleA + eaA*v01.x;  aA1.y = aA1.y*scaleA + eaA*v01.y;
        aA1.z = aA1.z*scaleA + eaA*v01.z;  aA1.w = aA1.w*scaleA + eaA*v01.w;
        mA = nmA;
    }

    // merge state B into state A (exact two-state softmax combine)
    if (mB > -INFINITY) {
        float nm = fmaxf(mA, mB);
        float eA = __expf(mA - nm);
        float eB = __expf(mB - nm);
        zA = zA * eA + zB * eB;
        aA0.x = aA0.x*eA + aB0.x*eB;  aA0.y = aA0.y*eA + aB0.y*eB;
        aA0.z = aA0.z*eA + aB0.z*eB;  aA0.w = aA0.w*eA + aB0.w*eB;
        aA1.x = aA1.x*eA + aB1.x*eB;  aA1.y = aA1.y*eA + aB1.y*eB;
        aA1.z = aA1.z*eA + aB1.z*eB;  aA1.w = aA1.w*eA + aB1.w*eB;
    }

    float inv = (zA > 0.0f) ? 1.0f / zA : 0.0f;
    float* ar = agg + (size_t)node * 256 + co;
    *(float4*)ar       = make_float4(aA0.x * inv, aA0.y * inv, aA0.z * inv, aA0.w * inv);
    *(float4*)(ar + 4) = make_float4(aA1.x * inv, aA1.y * inv, aA1.z * inv, aA1.w * inv);
}

// ---------------- driver ----------------
extern "C" void kernel_launch(void* const* d_in, const int* in_sizes, int n_in,
                              void* d_out, int out_size)
{
    const float* x0 = (const float*)d_in[0];
    const float* x1 = (const float*)d_in[1];
    const int*   e_dr = (const int*)d_in[2];
    const int*   e_rd = (const int*)d_in[3];
    const float* Wk = (const float*)d_in[4];
    const float* bk = (const float*)d_in[5];
    const float* Ar = (const float*)d_in[6];
    const float* Mr = (const float*)d_in[7];
    const float* pr = (const float*)d_in[8];
    const float* Wo = (const float*)d_in[9];
    const float* bo = (const float*)d_in[10];
    const float* sk = (const float*)d_in[11];
    float* out = (float*)d_out;

    float *gx, *gqv, *gagg, *gWeT, *gWoT, *gbe;
    __half* gkeh;
    cudaGetSymbolAddress((void**)&gx,   g_x);
    cudaGetSymbolAddress((void**)&gqv,  g_qv);
    cudaGetSymbolAddress((void**)&gkeh, g_keh);
    cudaGetSymbolAddress((void**)&gagg, g_agg);
    cudaGetSymbolAddress((void**)&gWeT, g_WeT);
    cudaGetSymbolAddress((void**)&gWoT, g_WoT);
    cudaGetSymbolAddress((void**)&gbe,  g_be);

    cudaFuncSetAttribute(gemm_kernel<true, false>, cudaFuncAttributeMaxDynamicSharedMemorySize, SMEM_DYN);
    cudaFuncSetAttribute(gemm_kernel<false, true>, cudaFuncAttributeMaxDynamicSharedMemorySize, SMEM_DYN);

    fold_kernel<<<96, 256>>>(Wk, bk, Ar, Mr);
    foldq_kernel<<<(2 * 6 * 256 * 256 + 255) / 256, 256>>>(Wk, bk, Wo);

    csr_zero_kernel<<<(2 * NP + 255) / 256, 256>>>();
    csr_hist_kernel<<<(EE + 255) / 256, 256>>>(e_dr + EE, e_rd + EE);
    csr_scan_kernel<<<2, 1024>>>();
    csr_scatter_kernel<<<(EE + 255) / 256, 256>>>(e_dr + EE, e_rd + EE);
    csr_sort_kernel<<<(2 * NP + 255) / 256, 256>>>(e_dr, e_rd);

    for (int l = 0; l < LL; l++) {
        const float* Ain0 = (l == 0) ? x0 : gx;
        const float* Ain1 = (l == 0) ? x1 : gx + (size_t)NP * FF;
        float* Cout0 = (l == LL - 1) ? out : gx;
        float* Cout1 = (l == LL - 1) ? out + (size_t)NN * FF : gx + (size_t)NP * FF;

        // kqv = x @ W_eff^T + b_eff  -> ke fp16 | q,ve fp32
        gemm_kernel<true, false><<<dim3(6, NP / 128, 2), 256, SMEM_DYN>>>(
            Ain0, Ain1,
            gWeT + (size_t)l * 2 * 768 * 256, gbe + (size_t)l * 2 * 768,
            gqv, gqv + (size_t)NP * 512,
            gkeh,
            (size_t)768 * 256, (size_t)768,
            nullptr, nullptr, nullptr);

        attn_kernel<<<(2 * NN * 32 + 255) / 256, 256>>>(pr + (size_t)l * 2 * HH);

        // x_next = relu( a*(gelu(agg) @ Wo^T + bo) + (1-a)*x )
        gemm_kernel<false, true><<<dim3(2, NP / 128, 2), 256, SMEM_DYN>>>(
            gagg, gagg + (size_t)NP * FF,
            gWoT + (size_t)l * 2 * 256 * 256, bo + (size_t)l * 2 * FF,
            Cout0, Cout1,
            nullptr,
            (size_t)256 * 256, (size_t)256,
            Ain0, Ain1, sk + l * 2);
    }
}